// round 3
// baseline (speedup 1.0000x reference)
#include <cuda_runtime.h>
#include <math.h>
#include <stdint.h>

#define BB 8
#define NN 8192
#define NP 2048
#define NS 32
#define DINC 61
#define DD 64

// ---------------- scratch (static device globals; no allocation) ----------------
__device__ float g_newxyz[BB * NP * 3];
__device__ int   g_gi[BB * NP * NS];
__device__ float g_feat2[BB * NP * DD];
__device__ float g_q[BB * NP * DD];
__device__ float g_k[BB * NP * DD];
__device__ float g_v[BB * NP * DD];
__device__ float g_o[BB * NP * DD];

// ---------------- FPS: one block per batch, xyz+dists in smem ----------------
__global__ void __launch_bounds__(1024) fps_kernel(const float* __restrict__ xyz,
                                                   float* __restrict__ out1) {
    extern __shared__ float sm[];
    float* sx   = sm;
    float* sy   = sm + NN;
    float* sz   = sm + 2 * NN;
    float* dist = sm + 3 * NN;
    float* wval = sm + 4 * NN;            // 32
    int*   widx = (int*)(wval + 32);      // 32
    int*   scur = widx + 32;              // 1

    const int b   = blockIdx.x;
    const int tid = threadIdx.x;
    const float* xb = xyz + (size_t)b * 3 * NN;

    for (int i = tid; i < NN; i += 1024) {
        sx[i] = xb[i];
        sy[i] = xb[NN + i];
        sz[i] = xb[2 * NN + i];
        dist[i] = 1e10f;
    }
    if (tid == 0) scur[0] = 0;
    __syncthreads();

    const int lane = tid & 31, wid = tid >> 5;

    for (int it = 0; it < NP; ++it) {
        const int cur = scur[0];
        const float c0 = sx[cur], c1 = sy[cur], c2 = sz[cur];
        if (tid == 0) {
            g_newxyz[((size_t)b * NP + it) * 3 + 0] = c0;
            g_newxyz[((size_t)b * NP + it) * 3 + 1] = c1;
            g_newxyz[((size_t)b * NP + it) * 3 + 2] = c2;
            out1[(size_t)b * 3 * NP + it]            = c0;
            out1[(size_t)b * 3 * NP + NP + it]       = c1;
            out1[(size_t)b * 3 * NP + 2 * NP + it]   = c2;
        }
        float best = -1.0f;
        int   bidx = 0;
        for (int i = tid; i < NN; i += 1024) {
            // match XLA elementwise: squares computed separately, summed (no FMA contraction)
            float dx = __fsub_rn(sx[i], c0);
            float dy = __fsub_rn(sy[i], c1);
            float dz = __fsub_rn(sz[i], c2);
            float d  = __fadd_rn(__fadd_rn(__fmul_rn(dx, dx), __fmul_rn(dy, dy)),
                                 __fmul_rn(dz, dz));
            float nd = fminf(dist[i], d);
            dist[i]  = nd;
            if (nd > best) { best = nd; bidx = i; }   // first-occurrence within thread
        }
#pragma unroll
        for (int off = 16; off; off >>= 1) {
            float ov = __shfl_down_sync(0xffffffffu, best, off);
            int   oi = __shfl_down_sync(0xffffffffu, bidx, off);
            if (ov > best || (ov == best && oi < bidx)) { best = ov; bidx = oi; }
        }
        if (lane == 0) { wval[wid] = best; widx[wid] = bidx; }
        __syncthreads();
        if (wid == 0) {
            best = wval[lane];
            bidx = widx[lane];
#pragma unroll
            for (int off = 16; off; off >>= 1) {
                float ov = __shfl_down_sync(0xffffffffu, best, off);
                int   oi = __shfl_down_sync(0xffffffffu, bidx, off);
                if (ov > best || (ov == best && oi < bidx)) { best = ov; bidx = oi; }
            }
            if (lane == 0) scur[0] = bidx;
        }
        __syncthreads();
    }
}

// ---------------- ball query: warp per center, xyz in smem ----------------
__global__ void __launch_bounds__(256) ballquery_kernel(const float* __restrict__ xyz) {
    extern __shared__ float sm[];
    float* sx = sm;
    float* sy = sm + NN;
    float* sz = sm + 2 * NN;

    const int b   = blockIdx.y;
    const int tid = threadIdx.x;
    const float* xb = xyz + (size_t)b * 3 * NN;
    for (int i = tid; i < NN; i += 256) {
        sx[i] = xb[i]; sy[i] = xb[NN + i]; sz[i] = xb[2 * NN + i];
    }
    __syncthreads();

    const int wid = tid >> 5, lane = tid & 31;
    const int s = blockIdx.x * 8 + wid;
    const float r2 = (float)(0.2 * 0.2);   // float32(0.04)

    const float c0 = g_newxyz[((size_t)b * NP + s) * 3 + 0];
    const float c1 = g_newxyz[((size_t)b * NP + s) * 3 + 1];
    const float c2 = g_newxyz[((size_t)b * NP + s) * 3 + 2];
    // |c|^2 from elementwise fusion: separate rounds (proven by exact FPS output)
    const float sqc = __fadd_rn(__fadd_rn(__fmul_rn(c0, c0), __fmul_rn(c1, c1)),
                                __fmul_rn(c2, c2));
    const size_t gbase = ((size_t)b * NP + s) * NS;

    int count = 0;
    int firstIdx = -1;
    for (int base = 0; base < NN && count < NS; base += 32) {
        const int i = base + lane;
        const float x = sx[i], y = sy[i], z = sz[i];
        const float sqx = __fadd_rn(__fadd_rn(__fmul_rn(x, x), __fmul_rn(y, y)),
                                    __fmul_rn(z, z));
        // cross term is a dot_general (K=3 GEMM) in the reference -> FMA chain from 0
        const float cx = fmaf(c2, z, fmaf(c1, y, __fmul_rn(c0, x)));
        const float sqr = __fsub_rn(__fadd_rn(sqc, sqx), __fmul_rn(2.0f, cx));
        const bool hit = !(sqr > r2);
        const unsigned mask = __ballot_sync(0xffffffffu, hit);
        if (firstIdx < 0 && mask) firstIdx = base + __ffs(mask) - 1;
        if (hit) {
            int slot = count + __popc(mask & ((1u << lane) - 1u));
            if (slot < NS) g_gi[gbase + slot] = i;
        }
        count += __popc(mask);
    }
    int cnt = count < NS ? count : NS;
    for (int j = cnt + lane; j < NS; j += 32) g_gi[gbase + j] = firstIdx;
}

// ---------------- grouped attention + max pool (block per group) ----------------
// smem layout (floats):
//  ft 0..2047 | qm 2048..4095 | km 4096..6175 (stride65) | vm 6176..8255 (stride65)
//  om 8256..10303 | Wq 10304 | Wk 14400 | Wv 18496 | Wo 22592 | Wp 26688 | Bp 26880
//  px 26944 | py 26976 | pz 27008 | aw 27040 (8x32) | red 27296 (4x64) | idx 27552 (32 int)
#define A1_SMEM_FLOATS 27584

__global__ void __launch_bounds__(256) attn1_kernel(
    const float* __restrict__ xyz, const float* __restrict__ points,
    const float* __restrict__ wq, const float* __restrict__ wk,
    const float* __restrict__ wv, const float* __restrict__ wo,
    const float* __restrict__ wp, const float* __restrict__ bp) {
    extern __shared__ float sm[];
    float* ft = sm;
    float* qm = sm + 2048;
    float* km = sm + 4096;
    float* vm = sm + 6176;
    float* om = sm + 8256;
    float* Wq = sm + 10304;
    float* Wk = sm + 14400;
    float* Wv = sm + 18496;
    float* Wo = sm + 22592;
    float* Wp = sm + 26688;
    float* Bp = sm + 26880;
    float* px = sm + 26944;
    float* py = sm + 26976;
    float* pz = sm + 27008;
    float* aw = sm + 27040;
    float* red = sm + 27296;
    int* sidx = (int*)(sm + 27552);

    const int g   = blockIdx.x;          // g = b*NP + s
    const int b   = g >> 11;
    const int tid = threadIdx.x;

    for (int i = tid; i < 4096; i += 256) {
        Wq[i] = wq[i]; Wk[i] = wk[i]; Wv[i] = wv[i]; Wo[i] = wo[i];
    }
    if (tid < 192) Wp[tid] = wp[tid];
    if (tid < 64)  Bp[tid] = bp[tid];
    if (tid < 32) {
        const int id = g_gi[(size_t)g * NS + tid];
        sidx[tid] = id;
        const float c0 = g_newxyz[(size_t)g * 3 + 0];
        const float c1 = g_newxyz[(size_t)g * 3 + 1];
        const float c2 = g_newxyz[(size_t)g * 3 + 2];
        const float X = xyz[(size_t)b * 3 * NN + id];
        const float Y = xyz[(size_t)b * 3 * NN + NN + id];
        const float Z = xyz[(size_t)b * 3 * NN + 2 * NN + id];
        px[tid] = X; py[tid] = Y; pz[tid] = Z;
        ft[tid * 64 + 0] = X - c0;
        ft[tid * 64 + 1] = Y - c1;
        ft[tid * 64 + 2] = Z - c2;
    }
    __syncthreads();

    // gather point features: ft[j][3+c] = points[b, c, idx_j]
    for (int i = tid; i < NS * DINC; i += 256) {
        const int c = i >> 5, j = i & 31;
        ft[j * 64 + 3 + c] = points[(size_t)b * DINC * NN + (size_t)c * NN + sidx[j]];
    }
    __syncthreads();

    // q/k/v projections
    for (int i = tid; i < 2048; i += 256) {
        const int t = i >> 6, d = i & 63;
        float aq = 0.f, ak = 0.f, av = 0.f;
        const float* frow = ft + t * 64;
#pragma unroll 8
        for (int e = 0; e < 64; ++e) {
            const float f = frow[e];
            aq += f * Wq[e * 64 + d];
            ak += f * Wk[e * 64 + d];
            av += f * Wv[e * 64 + d];
        }
        av += px[t] * Wp[d] + py[t] * Wp[64 + d] + pz[t] * Wp[128 + d] + Bp[d];
        qm[t * 64 + d] = aq;
        km[t * 65 + d] = ak;
        vm[t * 65 + d] = av;
    }
    __syncthreads();

    // attention: warp per query row (4 rows per warp)
    const int wid = tid >> 5, lane = tid & 31;
    for (int rep = 0; rep < 4; ++rep) {
        const int t = wid + rep * 8;
        const float* qrow = qm + t * 64;
        const float* krow = km + lane * 65;
        float sc = 0.f;
#pragma unroll 8
        for (int d = 0; d < 64; ++d) sc += qrow[d] * krow[d];
        sc *= 0.125f;
        float mx = sc;
#pragma unroll
        for (int off = 16; off; off >>= 1)
            mx = fmaxf(mx, __shfl_xor_sync(0xffffffffu, mx, off));
        const float p = expf(sc - mx);
        float ssum = p;
#pragma unroll
        for (int off = 16; off; off >>= 1)
            ssum += __shfl_xor_sync(0xffffffffu, ssum, off);
        aw[wid * 32 + lane] = p / ssum;
        __syncwarp();
        float a0 = 0.f, a1 = 0.f;
#pragma unroll 8
        for (int j = 0; j < 32; ++j) {
            const float a = aw[wid * 32 + j];
            a0 += a * vm[j * 65 + lane];
            a1 += a * vm[j * 65 + 32 + lane];
        }
        om[t * 64 + lane]      = a0;
        om[t * 64 + 32 + lane] = a1;
        __syncwarp();
    }
    __syncthreads();

    // z = ft + om @ Wo, then max over the 32 samples
    const int d = tid & 63, tg = tid >> 6;
    float m = -3.4e38f;
    for (int t = tg; t < 32; t += 4) {
        float acc = ft[t * 64 + d];
        const float* orow = om + t * 64;
#pragma unroll 8
        for (int e = 0; e < 64; ++e) acc += orow[e] * Wo[e * 64 + d];
        m = fmaxf(m, acc);
    }
    red[tg * 64 + d] = m;
    __syncthreads();
    if (tid < 64) {
        float mm = fmaxf(fmaxf(red[tid], red[64 + tid]),
                         fmaxf(red[128 + tid], red[192 + tid]));
        g_feat2[(size_t)g * 64 + tid] = mm;
    }
}

// ---------------- attn2 q/k/v projection (64-token tiles) ----------------
#define P2_SMEM_FLOATS 16832
__global__ void __launch_bounds__(256) proj2_kernel(
    const float* __restrict__ wq, const float* __restrict__ wk,
    const float* __restrict__ wv, const float* __restrict__ wp,
    const float* __restrict__ bp) {
    extern __shared__ float sm[];
    float* ft = sm;              // 4096
    float* Wq = sm + 4096;
    float* Wk = sm + 8192;
    float* Wv = sm + 12288;
    float* Wp = sm + 16384;      // 192
    float* Bp = sm + 16576;      // 64
    float* px = sm + 16640;
    float* py = sm + 16704;
    float* pz = sm + 16768;

    const int b  = blockIdx.x >> 5;
    const int t0 = (blockIdx.x & 31) << 6;
    const int tid = threadIdx.x;

    for (int i = tid; i < 4096; i += 256) {
        ft[i] = g_feat2[((size_t)b * NP + t0) * 64 + i];
        Wq[i] = wq[i]; Wk[i] = wk[i]; Wv[i] = wv[i];
    }
    if (tid < 192) Wp[tid] = wp[tid];
    if (tid < 64) {
        Bp[tid] = bp[tid];
        px[tid] = g_newxyz[((size_t)b * NP + t0 + tid) * 3 + 0];
        py[tid] = g_newxyz[((size_t)b * NP + t0 + tid) * 3 + 1];
        pz[tid] = g_newxyz[((size_t)b * NP + t0 + tid) * 3 + 2];
    }
    __syncthreads();

    for (int i = tid; i < 4096; i += 256) {
        const int t = i >> 6, d = i & 63;
        float aq = 0.f, ak = 0.f, av = 0.f;
        const float* frow = ft + t * 64;
#pragma unroll 8
        for (int e = 0; e < 64; ++e) {
            const float f = frow[e];
            aq += f * Wq[e * 64 + d];
            ak += f * Wk[e * 64 + d];
            av += f * Wv[e * 64 + d];
        }
        av += px[t] * Wp[d] + py[t] * Wp[64 + d] + pz[t] * Wp[128 + d] + Bp[d];
        const size_t o = ((size_t)b * NP + t0 + t) * 64 + d;
        g_q[o] = aq; g_k[o] = ak; g_v[o] = av;
    }
}

// ---------------- attn2: flash-style, warp per query ----------------
__global__ void __launch_bounds__(128) flash_kernel() {
    __shared__ float ks[4096];
    __shared__ float vsm[4096];
    const int b = blockIdx.y;
    const int wid = threadIdx.x >> 5, lane = threadIdx.x & 31;
    const int qi = blockIdx.x * 4 + wid;
    const size_t qoff = ((size_t)b * NP + qi) * 64;
    const float q0 = g_q[qoff + lane];
    const float q1 = g_q[qoff + 32 + lane];
    float m = -3.4e38f, l = 0.f, o0 = 0.f, o1 = 0.f;

    for (int chunk = 0; chunk < NP / 64; ++chunk) {
        __syncthreads();
        const size_t kb = ((size_t)b * NP + chunk * 64) * 64;
        for (int i = threadIdx.x; i < 4096; i += 128) {
            ks[i]  = g_k[kb + i];
            vsm[i] = g_v[kb + i];
        }
        __syncthreads();
#pragma unroll 4
        for (int j = 0; j < 64; ++j) {
            float s = q0 * ks[j * 64 + lane] + q1 * ks[j * 64 + 32 + lane];
#pragma unroll
            for (int off = 16; off; off >>= 1)
                s += __shfl_xor_sync(0xffffffffu, s, off);
            s *= 0.125f;
            if (s <= m) {
                const float p = expf(s - m);
                l  += p;
                o0 += p * vsm[j * 64 + lane];
                o1 += p * vsm[j * 64 + 32 + lane];
            } else {
                const float corr = expf(m - s);
                l  = l * corr + 1.f;
                o0 = o0 * corr + vsm[j * 64 + lane];
                o1 = o1 * corr + vsm[j * 64 + 32 + lane];
                m  = s;
            }
        }
    }
    g_o[qoff + lane]      = o0 / l;
    g_o[qoff + 32 + lane] = o1 / l;
}

// ---------------- final: z = feat2 + o @ Wo, write transposed ----------------
#define FIN_SMEM_FLOATS 12352
__global__ void __launch_bounds__(256) final_kernel(const float* __restrict__ wo,
                                                    float* __restrict__ out2) {
    extern __shared__ float sm[];
    float* ot = sm;          // 4096
    float* Wo = sm + 4096;   // 4096
    float* z  = sm + 8192;   // 64*65

    const int b  = blockIdx.x >> 5;
    const int t0 = (blockIdx.x & 31) << 6;
    const int tid = threadIdx.x;

    for (int i = tid; i < 4096; i += 256) {
        ot[i] = g_o[((size_t)b * NP + t0) * 64 + i];
        Wo[i] = wo[i];
    }
    __syncthreads();
    for (int i = tid; i < 4096; i += 256) {
        const int t = i >> 6, d = i & 63;
        float acc = g_feat2[((size_t)b * NP + t0 + t) * 64 + d];
        const float* orow = ot + t * 64;
#pragma unroll 8
        for (int e = 0; e < 64; ++e) acc += orow[e] * Wo[e * 64 + d];
        z[t * 65 + d] = acc;
    }
    __syncthreads();
    for (int i = tid; i < 4096; i += 256) {
        const int d = i >> 6, tt = i & 63;
        out2[(size_t)b * DD * NP + (size_t)d * NP + t0 + tt] = z[tt * 65 + d];
    }
}

// ---------------- launch ----------------
extern "C" void kernel_launch(void* const* d_in, const int* in_sizes, int n_in,
                              void* d_out, int out_size) {
    const float* xyz    = (const float*)d_in[0];
    const float* points = (const float*)d_in[1];
    const float* w1q = (const float*)d_in[2];
    const float* w1k = (const float*)d_in[3];
    const float* w1v = (const float*)d_in[4];
    const float* w1o = (const float*)d_in[5];
    const float* w1p = (const float*)d_in[6];
    const float* b1p = (const float*)d_in[7];
    const float* w2q = (const float*)d_in[8];
    const float* w2k = (const float*)d_in[9];
    const float* w2v = (const float*)d_in[10];
    const float* w2o = (const float*)d_in[11];
    const float* w2p = (const float*)d_in[12];
    const float* b2p = (const float*)d_in[13];

    float* out  = (float*)d_out;
    float* out2 = out + (size_t)BB * 3 * NP;

    const int smFps = (4 * NN + 32) * 4 + 32 * 4 + 16;
    const int smBq  = 3 * NN * 4;
    const int smA1  = A1_SMEM_FLOATS * 4;
    const int smP2  = P2_SMEM_FLOATS * 4;
    const int smFin = FIN_SMEM_FLOATS * 4;

    cudaFuncSetAttribute(fps_kernel,       cudaFuncAttributeMaxDynamicSharedMemorySize, smFps);
    cudaFuncSetAttribute(ballquery_kernel, cudaFuncAttributeMaxDynamicSharedMemorySize, smBq);
    cudaFuncSetAttribute(attn1_kernel,     cudaFuncAttributeMaxDynamicSharedMemorySize, smA1);
    cudaFuncSetAttribute(proj2_kernel,     cudaFuncAttributeMaxDynamicSharedMemorySize, smP2);
    cudaFuncSetAttribute(final_kernel,     cudaFuncAttributeMaxDynamicSharedMemorySize, smFin);

    fps_kernel<<<BB, 1024, smFps>>>(xyz, out);
    ballquery_kernel<<<dim3(NP / 8, BB), 256, smBq>>>(xyz);
    attn1_kernel<<<BB * NP, 256, smA1>>>(xyz, points, w1q, w1k, w1v, w1o, w1p, b1p);
    proj2_kernel<<<BB * (NP / 64), 256, smP2>>>(w2q, w2k, w2v, w2p, b2p);
    flash_kernel<<<dim3(NP / 4, BB), 128>>>();
    final_kernel<<<BB * (NP / 64), 256, smFin>>>(w2o, out2);
}

// round 4
// speedup vs baseline: 1.4716x; 1.4716x over previous
#include <cuda_runtime.h>
#include <math.h>
#include <stdint.h>

#define BB 8
#define NN 8192
#define NP 2048
#define NS 32
#define DINC 61
#define DD 64

__device__ float g_newxyz[BB * NP * 3];
__device__ int   g_gi[BB * NP * NS];
__device__ float g_feat2[BB * NP * DD];
__device__ float g_qp[BB * NP * DD];
__device__ float g_v[BB * NP * DD];
__device__ float g_o[BB * NP * DD];
__device__ float g_M1[DD * DD];
__device__ float g_M2[DD * DD];

// ---------------- M = 0.125 * Wq @ Wk^T ----------------
__global__ void __launch_bounds__(256) mprep_kernel(
    const float* __restrict__ q1, const float* __restrict__ k1,
    const float* __restrict__ q2, const float* __restrict__ k2) {
    __shared__ float sq[4096], sk[4096];
    const float* q = blockIdx.x ? q2 : q1;
    const float* k = blockIdx.x ? k2 : k1;
    float* M = blockIdx.x ? g_M2 : g_M1;
    const int tid = threadIdx.x;
    for (int i = tid; i < 4096; i += 256) { sq[i] = q[i]; sk[i] = k[i]; }
    __syncthreads();
    for (int o = 0; o < 16; ++o) {
        const int idx = tid + o * 256;
        const int a = idx >> 6, c = idx & 63;
        float s = 0.f;
#pragma unroll 8
        for (int d = 0; d < 64; ++d) s += sq[a * 64 + d] * sk[c * 64 + d];
        M[idx] = 0.125f * s;
    }
}

// ---------------- FPS: registers for coords+dists ----------------
__global__ void __launch_bounds__(1024) fps_kernel(const float* __restrict__ xyz,
                                                   float* __restrict__ out1) {
    extern __shared__ float sm[];
    float* sx   = sm;
    float* sy   = sm + NN;
    float* sz   = sm + 2 * NN;
    float* wmax = sm + 3 * NN;
    float* bmax = sm + 3 * NN + 32;
    int*   sidx = (int*)(sm + 3 * NN + 33);

    const int b   = blockIdx.x;
    const int tid = threadIdx.x;
    const int lane = tid & 31, wid = tid >> 5;
    const float* xb = xyz + (size_t)b * 3 * NN;

    float rx[8], ry[8], rz[8], pd[8];
#pragma unroll
    for (int k = 0; k < 8; ++k) {
        const int i = tid + k * 1024;
        rx[k] = xb[i]; ry[k] = xb[NN + i]; rz[k] = xb[2 * NN + i];
        sx[i] = rx[k]; sy[i] = ry[k]; sz[i] = rz[k];
        pd[k] = 1e10f;
    }
    if (tid == 0) sidx[0] = 0;
    __syncthreads();

    for (int it = 0; it < NP; ++it) {
        const int cur = sidx[0];
        const float c0 = sx[cur], c1 = sy[cur], c2 = sz[cur];
        if (tid == 0) {
            g_newxyz[((size_t)b * NP + it) * 3 + 0] = c0;
            g_newxyz[((size_t)b * NP + it) * 3 + 1] = c1;
            g_newxyz[((size_t)b * NP + it) * 3 + 2] = c2;
            out1[(size_t)b * 3 * NP + it]          = c0;
            out1[(size_t)b * 3 * NP + NP + it]     = c1;
            out1[(size_t)b * 3 * NP + 2 * NP + it] = c2;
        }
        float tmax = -1.0f;
#pragma unroll
        for (int k = 0; k < 8; ++k) {
            // XLA elementwise: separate rounds, no FMA contraction (bit-exact proven)
            float dx = __fsub_rn(rx[k], c0);
            float dy = __fsub_rn(ry[k], c1);
            float dz = __fsub_rn(rz[k], c2);
            float d  = __fadd_rn(__fadd_rn(__fmul_rn(dx, dx), __fmul_rn(dy, dy)),
                                 __fmul_rn(dz, dz));
            pd[k] = fminf(pd[k], d);
            tmax  = fmaxf(tmax, pd[k]);
        }
        float wv = tmax;
#pragma unroll
        for (int off = 16; off; off >>= 1)
            wv = fmaxf(wv, __shfl_xor_sync(0xffffffffu, wv, off));
        if (lane == 0) wmax[wid] = wv;
        __syncthreads();
        if (wid == 0) {
            float v = wmax[lane];
#pragma unroll
            for (int off = 16; off; off >>= 1)
                v = fmaxf(v, __shfl_xor_sync(0xffffffffu, v, off));
            if (lane == 0) { bmax[0] = v; sidx[0] = 0x7fffffff; }
        }
        __syncthreads();
        const float bm = bmax[0];
        if (tmax == bm) {
#pragma unroll
            for (int k = 0; k < 8; ++k)
                if (pd[k] == bm) atomicMin(sidx, tid + k * 1024);
        }
        __syncthreads();
    }
}

// ---------------- ball query (unchanged, proven) ----------------
__global__ void __launch_bounds__(256) ballquery_kernel(const float* __restrict__ xyz) {
    extern __shared__ float sm[];
    float* sx = sm;
    float* sy = sm + NN;
    float* sz = sm + 2 * NN;

    const int b   = blockIdx.y;
    const int tid = threadIdx.x;
    const float* xb = xyz + (size_t)b * 3 * NN;
    for (int i = tid; i < NN; i += 256) {
        sx[i] = xb[i]; sy[i] = xb[NN + i]; sz[i] = xb[2 * NN + i];
    }
    __syncthreads();

    const int wid = tid >> 5, lane = tid & 31;
    const int s = blockIdx.x * 8 + wid;
    const float r2 = (float)(0.2 * 0.2);

    const float c0 = g_newxyz[((size_t)b * NP + s) * 3 + 0];
    const float c1 = g_newxyz[((size_t)b * NP + s) * 3 + 1];
    const float c2 = g_newxyz[((size_t)b * NP + s) * 3 + 2];
    const float sqc = __fadd_rn(__fadd_rn(__fmul_rn(c0, c0), __fmul_rn(c1, c1)),
                                __fmul_rn(c2, c2));
    const size_t gbase = ((size_t)b * NP + s) * NS;

    int count = 0;
    int firstIdx = -1;
    for (int base = 0; base < NN && count < NS; base += 32) {
        const int i = base + lane;
        const float x = sx[i], y = sy[i], z = sz[i];
        const float sqx = __fadd_rn(__fadd_rn(__fmul_rn(x, x), __fmul_rn(y, y)),
                                    __fmul_rn(z, z));
        const float cx = fmaf(c2, z, fmaf(c1, y, __fmul_rn(c0, x)));
        const float sqr = __fsub_rn(__fadd_rn(sqc, sqx), __fmul_rn(2.0f, cx));
        const bool hit = !(sqr > r2);
        const unsigned mask = __ballot_sync(0xffffffffu, hit);
        if (firstIdx < 0 && mask) firstIdx = base + __ffs(mask) - 1;
        if (hit) {
            int slot = count + __popc(mask & ((1u << lane) - 1u));
            if (slot < NS) g_gi[gbase + slot] = i;
        }
        count += __popc(mask);
    }
    int cnt = count < NS ? count : NS;
    for (int j = cnt + lane; j < NS; j += 32) g_gi[gbase + j] = firstIdx;
}

// ---------------- attn1: M-folded, register-tiled, fused max-pool ----------------
#define A1_SMEM_FLOATS 25348
__global__ void __launch_bounds__(256) attn1_kernel(
    const float* __restrict__ xyz, const float* __restrict__ points,
    const float* __restrict__ wv, const float* __restrict__ wo,
    const float* __restrict__ wp, const float* __restrict__ bp) {
    extern __shared__ float sm[];
    float* ft  = sm;            // 32x68
    float* ftT = sm + 2176;     // 64x36
    float* tm  = sm + 4480;     // 32x68
    float* vm  = sm + 6656;     // 32x68
    float* om  = sm + 8832;     // 32x68
    float* sc  = sm + 11008;    // 32x36
    float* Ms  = sm + 12160;    // 4096
    float* Wv  = sm + 16256;    // 4096
    float* Wo  = sm + 20352;    // 4096
    float* Wp  = sm + 24448;    // 192
    float* Bp  = sm + 24640;    // 64
    float* px  = sm + 24704;
    float* py  = sm + 24736;
    float* pz  = sm + 24768;
    float* red = sm + 24800;    // 8x64
    int* sidx  = (int*)(sm + 25312);

    const int g   = blockIdx.x;
    const int b   = g >> 11;
    const int tid = threadIdx.x;
    const int lane = tid & 31, wid = tid >> 5;

    for (int i = tid; i < 4096; i += 256) {
        Ms[i] = g_M1[i]; Wv[i] = wv[i]; Wo[i] = wo[i];
    }
    if (tid < 192) Wp[tid] = wp[tid];
    if (tid < 64)  Bp[tid] = bp[tid];
    if (tid < 32) {
        const int id = g_gi[(size_t)g * NS + tid];
        sidx[tid] = id;
        const float c0 = g_newxyz[(size_t)g * 3 + 0];
        const float c1 = g_newxyz[(size_t)g * 3 + 1];
        const float c2 = g_newxyz[(size_t)g * 3 + 2];
        const float X = xyz[(size_t)b * 3 * NN + id];
        const float Y = xyz[(size_t)b * 3 * NN + NN + id];
        const float Z = xyz[(size_t)b * 3 * NN + 2 * NN + id];
        px[tid] = X; py[tid] = Y; pz[tid] = Z;
        ft[tid * 68 + 0] = X - c0;
        ft[tid * 68 + 1] = Y - c1;
        ft[tid * 68 + 2] = Z - c2;
    }
    __syncthreads();

    for (int i = tid; i < NS * DINC; i += 256) {
        const int c = i >> 5, j = i & 31;
        ft[j * 68 + 3 + c] = points[(size_t)b * DINC * NN + (size_t)c * NN + sidx[j]];
    }
    __syncthreads();

    const int t  = tid >> 3;
    const int d0 = (tid & 7) * 8;

    {   // tm = ft @ Ms ; vm = ft @ Wv + pos + bias
        float at[8] = {0,0,0,0,0,0,0,0};
        float av[8] = {0,0,0,0,0,0,0,0};
        const float* fr = ft + t * 68;
#pragma unroll 4
        for (int e = 0; e < 64; ++e) {
            const float f = fr[e];
            const float4 m0 = *(const float4*)&Ms[e * 64 + d0];
            const float4 m1 = *(const float4*)&Ms[e * 64 + d0 + 4];
            const float4 v0 = *(const float4*)&Wv[e * 64 + d0];
            const float4 v1 = *(const float4*)&Wv[e * 64 + d0 + 4];
            at[0] += f * m0.x; at[1] += f * m0.y; at[2] += f * m0.z; at[3] += f * m0.w;
            at[4] += f * m1.x; at[5] += f * m1.y; at[6] += f * m1.z; at[7] += f * m1.w;
            av[0] += f * v0.x; av[1] += f * v0.y; av[2] += f * v0.z; av[3] += f * v0.w;
            av[4] += f * v1.x; av[5] += f * v1.y; av[6] += f * v1.z; av[7] += f * v1.w;
        }
        const float X = px[t], Y = py[t], Z = pz[t];
#pragma unroll
        for (int i = 0; i < 8; ++i)
            av[i] += X * Wp[d0 + i] + Y * Wp[64 + d0 + i] + Z * Wp[128 + d0 + i] + Bp[d0 + i];
        *(float4*)&tm[t * 68 + d0]     = make_float4(at[0], at[1], at[2], at[3]);
        *(float4*)&tm[t * 68 + d0 + 4] = make_float4(at[4], at[5], at[6], at[7]);
        *(float4*)&vm[t * 68 + d0]     = make_float4(av[0], av[1], av[2], av[3]);
        *(float4*)&vm[t * 68 + d0 + 4] = make_float4(av[4], av[5], av[6], av[7]);
    }
#pragma unroll
    for (int r = 0; r < 8; ++r) {
        const int idx = tid + r * 256;
        const int e = idx >> 5, j = idx & 31;
        ftT[e * 36 + j] = ft[j * 68 + e];
    }
    __syncthreads();

    {   // scores[t][j] = tm[t] . ft[j]
        const int j0 = (tid & 7) * 4;
        float s0 = 0.f, s1 = 0.f, s2 = 0.f, s3 = 0.f;
        const float* tr = tm + t * 68;
#pragma unroll 8
        for (int e = 0; e < 64; ++e) {
            const float a = tr[e];
            const float4 bb = *(const float4*)&ftT[e * 36 + j0];
            s0 += a * bb.x; s1 += a * bb.y; s2 += a * bb.z; s3 += a * bb.w;
        }
        *(float4*)&sc[t * 36 + j0] = make_float4(s0, s1, s2, s3);
    }
    __syncthreads();

    for (int rep = 0; rep < 4; ++rep) {   // softmax rows
        const int r = wid * 4 + rep;
        float v = sc[r * 36 + lane];
        float mx = v;
#pragma unroll
        for (int off = 16; off; off >>= 1)
            mx = fmaxf(mx, __shfl_xor_sync(0xffffffffu, mx, off));
        const float p = __expf(v - mx);
        float ssum = p;
#pragma unroll
        for (int off = 16; off; off >>= 1)
            ssum += __shfl_xor_sync(0xffffffffu, ssum, off);
        sc[r * 36 + lane] = p * __fdividef(1.0f, ssum);
    }
    __syncthreads();

    {   // om[t] = p[t] @ vm
        float o[8] = {0,0,0,0,0,0,0,0};
        const float* pr = sc + t * 36;
#pragma unroll
        for (int j4 = 0; j4 < 8; ++j4) {
            float pa[4];
            *(float4*)pa = *(const float4*)&pr[j4 * 4];
#pragma unroll
            for (int jj = 0; jj < 4; ++jj) {
                const int j = j4 * 4 + jj;
                const float4 v0 = *(const float4*)&vm[j * 68 + d0];
                const float4 v1 = *(const float4*)&vm[j * 68 + d0 + 4];
                const float p = pa[jj];
                o[0] += p * v0.x; o[1] += p * v0.y; o[2] += p * v0.z; o[3] += p * v0.w;
                o[4] += p * v1.x; o[5] += p * v1.y; o[6] += p * v1.z; o[7] += p * v1.w;
            }
        }
        *(float4*)&om[t * 68 + d0]     = make_float4(o[0], o[1], o[2], o[3]);
        *(float4*)&om[t * 68 + d0 + 4] = make_float4(o[4], o[5], o[6], o[7]);
    }
    __syncthreads();

    {   // z = ft + om @ Wo, max over t
        float z[8];
        const float4 f0 = *(const float4*)&ft[t * 68 + d0];
        const float4 f1 = *(const float4*)&ft[t * 68 + d0 + 4];
        z[0] = f0.x; z[1] = f0.y; z[2] = f0.z; z[3] = f0.w;
        z[4] = f1.x; z[5] = f1.y; z[6] = f1.z; z[7] = f1.w;
        const float* orow = om + t * 68;
#pragma unroll 4
        for (int e = 0; e < 64; ++e) {
            const float a = orow[e];
            const float4 w0 = *(const float4*)&Wo[e * 64 + d0];
            const float4 w1 = *(const float4*)&Wo[e * 64 + d0 + 4];
            z[0] += a * w0.x; z[1] += a * w0.y; z[2] += a * w0.z; z[3] += a * w0.w;
            z[4] += a * w1.x; z[5] += a * w1.y; z[6] += a * w1.z; z[7] += a * w1.w;
        }
#pragma unroll
        for (int i = 0; i < 8; ++i) {
            z[i] = fmaxf(z[i], __shfl_xor_sync(0xffffffffu, z[i], 8));
            z[i] = fmaxf(z[i], __shfl_xor_sync(0xffffffffu, z[i], 16));
        }
        if (lane < 8) {
            *(float4*)&red[wid * 64 + d0]     = make_float4(z[0], z[1], z[2], z[3]);
            *(float4*)&red[wid * 64 + d0 + 4] = make_float4(z[4], z[5], z[6], z[7]);
        }
    }
    __syncthreads();
    if (tid < 64) {
        float m = red[tid];
#pragma unroll
        for (int w = 1; w < 8; ++w) m = fmaxf(m, red[w * 64 + tid]);
        g_feat2[(size_t)g * 64 + tid] = m;
    }
}

// ---------------- proj2: q' = feat2 @ M2, v = feat2 @ Wv2 + pos ----------------
__global__ void __launch_bounds__(256) proj2_kernel(
    const float* __restrict__ wv2, const float* __restrict__ wp2,
    const float* __restrict__ bp2) {
    __shared__ float ft2[32 * 68];
    __shared__ float Ms[4096], Wv[4096], Wp[192], Bp[64];
    __shared__ float px[32], py[32], pz[32];

    const int b  = blockIdx.x >> 6;
    const int t0 = (blockIdx.x & 63) * 32;
    const int tid = threadIdx.x;

    for (int i = tid; i < 4096; i += 256) { Ms[i] = g_M2[i]; Wv[i] = wv2[i]; }
    if (tid < 192) Wp[tid] = wp2[tid];
    if (tid < 64)  Bp[tid] = bp2[tid];
#pragma unroll
    for (int r = 0; r < 2; ++r) {
        const int f4 = tid + r * 256;
        const int tt = f4 >> 4, c4 = (f4 & 15) * 4;
        *(float4*)&ft2[tt * 68 + c4] =
            *(const float4*)&g_feat2[((size_t)(b * NP + t0 + tt)) * 64 + c4];
    }
    if (tid < 32) {
        px[tid] = g_newxyz[((size_t)(b * NP + t0 + tid)) * 3 + 0];
        py[tid] = g_newxyz[((size_t)(b * NP + t0 + tid)) * 3 + 1];
        pz[tid] = g_newxyz[((size_t)(b * NP + t0 + tid)) * 3 + 2];
    }
    __syncthreads();

    const int t  = tid >> 3;
    const int d0 = (tid & 7) * 8;
    float aq[8] = {0,0,0,0,0,0,0,0};
    float av[8] = {0,0,0,0,0,0,0,0};
    const float* fr = ft2 + t * 68;
#pragma unroll 4
    for (int e = 0; e < 64; ++e) {
        const float f = fr[e];
        const float4 m0 = *(const float4*)&Ms[e * 64 + d0];
        const float4 m1 = *(const float4*)&Ms[e * 64 + d0 + 4];
        const float4 v0 = *(const float4*)&Wv[e * 64 + d0];
        const float4 v1 = *(const float4*)&Wv[e * 64 + d0 + 4];
        aq[0] += f * m0.x; aq[1] += f * m0.y; aq[2] += f * m0.z; aq[3] += f * m0.w;
        aq[4] += f * m1.x; aq[5] += f * m1.y; aq[6] += f * m1.z; aq[7] += f * m1.w;
        av[0] += f * v0.x; av[1] += f * v0.y; av[2] += f * v0.z; av[3] += f * v0.w;
        av[4] += f * v1.x; av[5] += f * v1.y; av[6] += f * v1.z; av[7] += f * v1.w;
    }
    const float X = px[t], Y = py[t], Z = pz[t];
#pragma unroll
    for (int i = 0; i < 8; ++i)
        av[i] += X * Wp[d0 + i] + Y * Wp[64 + d0 + i] + Z * Wp[128 + d0 + i] + Bp[d0 + i];

    const size_t o = ((size_t)(b * NP + t0 + t)) * 64 + d0;
    *(float4*)&g_qp[o]     = make_float4(aq[0], aq[1], aq[2], aq[3]);
    *(float4*)&g_qp[o + 4] = make_float4(aq[4], aq[5], aq[6], aq[7]);
    *(float4*)&g_v[o]      = make_float4(av[0], av[1], av[2], av[3]);
    *(float4*)&g_v[o + 4]  = make_float4(av[4], av[5], av[6], av[7]);
}

// ---------------- attn2 flash: 32 q/block, lane-per-key ----------------
__global__ void __launch_bounds__(256) flash_kernel() {
    __shared__ float qs[32 * 68];
    __shared__ float ks[32 * 68];
    __shared__ float vs[32 * 68];
    __shared__ float ps[8 * 144];

    const int b   = blockIdx.y;
    const int q0  = blockIdx.x * 32;
    const int tid = threadIdx.x;
    const int lane = tid & 31, wid = tid >> 5;

#pragma unroll
    for (int r = 0; r < 2; ++r) {
        const int f4 = tid + r * 256;
        const int tt = f4 >> 4, c4 = (f4 & 15) * 4;
        *(float4*)&qs[tt * 68 + c4] =
            *(const float4*)&g_qp[((size_t)(b * NP + q0 + tt)) * 64 + c4];
    }

    float m0q = -1e30f, m1q = -1e30f, m2q = -1e30f, m3q = -1e30f;
    float l0 = 0.f, l1 = 0.f, l2 = 0.f, l3 = 0.f;
    float oa0 = 0.f, oa1 = 0.f, oa2 = 0.f, oa3 = 0.f;
    float ob0 = 0.f, ob1 = 0.f, ob2 = 0.f, ob3 = 0.f;

    const float* q0r = qs + (wid * 4 + 0) * 68;
    const float* q1r = qs + (wid * 4 + 1) * 68;
    const float* q2r = qs + (wid * 4 + 2) * 68;
    const float* q3r = qs + (wid * 4 + 3) * 68;
    float* pw = ps + wid * 144;

    for (int c = 0; c < NP / 32; ++c) {
        __syncthreads();
        const int kb = b * NP + c * 32;
#pragma unroll
        for (int r = 0; r < 2; ++r) {
            const int f4 = tid + r * 256;
            const int tt = f4 >> 4, c4 = (f4 & 15) * 4;
            *(float4*)&ks[tt * 68 + c4] =
                *(const float4*)&g_feat2[((size_t)(kb + tt)) * 64 + c4];
            *(float4*)&vs[tt * 68 + c4] =
                *(const float4*)&g_v[((size_t)(kb + tt)) * 64 + c4];
        }
        __syncthreads();

        float s0 = 0.f, s1 = 0.f, s2 = 0.f, s3 = 0.f;
        const float* krow = ks + lane * 68;
#pragma unroll
        for (int e4 = 0; e4 < 16; ++e4) {
            const float4 k4 = *(const float4*)&krow[e4 * 4];
            float4 a;
            a = *(const float4*)&q0r[e4 * 4];
            s0 += a.x * k4.x + a.y * k4.y + a.z * k4.z + a.w * k4.w;
            a = *(const float4*)&q1r[e4 * 4];
            s1 += a.x * k4.x + a.y * k4.y + a.z * k4.z + a.w * k4.w;
            a = *(const float4*)&q2r[e4 * 4];
            s2 += a.x * k4.x + a.y * k4.y + a.z * k4.z + a.w * k4.w;
            a = *(const float4*)&q3r[e4 * 4];
            s3 += a.x * k4.x + a.y * k4.y + a.z * k4.z + a.w * k4.w;
        }

#define FLASH_SM(S, M, L, OA, OB, QQ)                                        \
        {                                                                    \
            float cm = S;                                                    \
            cm = fmaxf(cm, __shfl_xor_sync(0xffffffffu, cm, 16));            \
            cm = fmaxf(cm, __shfl_xor_sync(0xffffffffu, cm, 8));             \
            cm = fmaxf(cm, __shfl_xor_sync(0xffffffffu, cm, 4));             \
            cm = fmaxf(cm, __shfl_xor_sync(0xffffffffu, cm, 2));             \
            cm = fmaxf(cm, __shfl_xor_sync(0xffffffffu, cm, 1));             \
            const float mn = fmaxf(M, cm);                                   \
            const float corr = __expf(M - mn);                               \
            const float p = __expf(S - mn);                                  \
            float sp = p;                                                    \
            sp += __shfl_xor_sync(0xffffffffu, sp, 16);                      \
            sp += __shfl_xor_sync(0xffffffffu, sp, 8);                       \
            sp += __shfl_xor_sync(0xffffffffu, sp, 4);                       \
            sp += __shfl_xor_sync(0xffffffffu, sp, 2);                       \
            sp += __shfl_xor_sync(0xffffffffu, sp, 1);                       \
            L = L * corr + sp;                                               \
            OA *= corr; OB *= corr;                                          \
            pw[QQ * 36 + lane] = p;                                          \
            M = mn;                                                          \
        }
        FLASH_SM(s0, m0q, l0, oa0, ob0, 0)
        FLASH_SM(s1, m1q, l1, oa1, ob1, 1)
        FLASH_SM(s2, m2q, l2, oa2, ob2, 2)
        FLASH_SM(s3, m3q, l3, oa3, ob3, 3)
#undef FLASH_SM
        __syncwarp();

#pragma unroll
        for (int j4 = 0; j4 < 8; ++j4) {
            float pa0[4], pa1[4], pa2[4], pa3[4];
            *(float4*)pa0 = *(const float4*)&pw[0   + j4 * 4];
            *(float4*)pa1 = *(const float4*)&pw[36  + j4 * 4];
            *(float4*)pa2 = *(const float4*)&pw[72  + j4 * 4];
            *(float4*)pa3 = *(const float4*)&pw[108 + j4 * 4];
#pragma unroll
            for (int jj = 0; jj < 4; ++jj) {
                const int j = j4 * 4 + jj;
                const float va = vs[j * 68 + lane];
                const float vb = vs[j * 68 + 32 + lane];
                oa0 += pa0[jj] * va; ob0 += pa0[jj] * vb;
                oa1 += pa1[jj] * va; ob1 += pa1[jj] * vb;
                oa2 += pa2[jj] * va; ob2 += pa2[jj] * vb;
                oa3 += pa3[jj] * va; ob3 += pa3[jj] * vb;
            }
        }
        __syncwarp();
    }

    const size_t ob = ((size_t)(b * NP + q0 + wid * 4)) * 64;
    g_o[ob + lane]       = oa0 / l0;
    g_o[ob + 32 + lane]  = ob0 / l0;
    g_o[ob + 64 + lane]  = oa1 / l1;
    g_o[ob + 96 + lane]  = ob1 / l1;
    g_o[ob + 128 + lane] = oa2 / l2;
    g_o[ob + 160 + lane] = ob2 / l2;
    g_o[ob + 192 + lane] = oa3 / l3;
    g_o[ob + 224 + lane] = ob3 / l3;
}

// ---------------- final: z = feat2 + o @ Wo2, transposed store ----------------
__global__ void __launch_bounds__(256) final_kernel(const float* __restrict__ wo,
                                                    float* __restrict__ out2) {
    __shared__ float ot[32 * 68];
    __shared__ float Wo[4096];
    __shared__ float zs[32 * 68];

    const int b  = blockIdx.x >> 6;
    const int t0 = (blockIdx.x & 63) * 32;
    const int tid = threadIdx.x;

    for (int i = tid; i < 4096; i += 256) Wo[i] = wo[i];
#pragma unroll
    for (int r = 0; r < 2; ++r) {
        const int f4 = tid + r * 256;
        const int tt = f4 >> 4, c4 = (f4 & 15) * 4;
        *(float4*)&ot[tt * 68 + c4] =
            *(const float4*)&g_o[((size_t)(b * NP + t0 + tt)) * 64 + c4];
    }
    __syncthreads();

    const int t  = tid >> 3;
    const int d0 = (tid & 7) * 8;
    float z[8];
    {
        const size_t fo = ((size_t)(b * NP + t0 + t)) * 64 + d0;
        const float4 f0 = *(const float4*)&g_feat2[fo];
        const float4 f1 = *(const float4*)&g_feat2[fo + 4];
        z[0] = f0.x; z[1] = f0.y; z[2] = f0.z; z[3] = f0.w;
        z[4] = f1.x; z[5] = f1.y; z[6] = f1.z; z[7] = f1.w;
    }
    const float* orow = ot + t * 68;
#pragma unroll 4
    for (int e = 0; e < 64; ++e) {
        const float a = orow[e];
        const float4 w0 = *(const float4*)&Wo[e * 64 + d0];
        const float4 w1 = *(const float4*)&Wo[e * 64 + d0 + 4];
        z[0] += a * w0.x; z[1] += a * w0.y; z[2] += a * w0.z; z[3] += a * w0.w;
        z[4] += a * w1.x; z[5] += a * w1.y; z[6] += a * w1.z; z[7] += a * w1.w;
    }
    *(float4*)&zs[t * 68 + d0]     = make_float4(z[0], z[1], z[2], z[3]);
    *(float4*)&zs[t * 68 + d0 + 4] = make_float4(z[4], z[5], z[6], z[7]);
    __syncthreads();

    for (int i = tid; i < 2048; i += 256) {
        const int d = i >> 5, tt = i & 31;
        out2[(size_t)b * DD * NP + (size_t)d * NP + t0 + tt] = zs[tt * 68 + d];
    }
}

// ---------------- launch ----------------
extern "C" void kernel_launch(void* const* d_in, const int* in_sizes, int n_in,
                              void* d_out, int out_size) {
    const float* xyz    = (const float*)d_in[0];
    const float* points = (const float*)d_in[1];
    const float* w1q = (const float*)d_in[2];
    const float* w1k = (const float*)d_in[3];
    const float* w1v = (const float*)d_in[4];
    const float* w1o = (const float*)d_in[5];
    const float* w1p = (const float*)d_in[6];
    const float* b1p = (const float*)d_in[7];
    const float* w2q = (const float*)d_in[8];
    const float* w2k = (const float*)d_in[9];
    const float* w2v = (const float*)d_in[10];
    const float* w2o = (const float*)d_in[11];
    const float* w2p = (const float*)d_in[12];
    const float* b2p = (const float*)d_in[13];

    float* out  = (float*)d_out;
    float* out2 = out + (size_t)BB * 3 * NP;

    const int smFps = (3 * NN + 34) * 4;
    const int smBq  = 3 * NN * 4;
    const int smA1  = A1_SMEM_FLOATS * 4;

    cudaFuncSetAttribute(fps_kernel,       cudaFuncAttributeMaxDynamicSharedMemorySize, smFps);
    cudaFuncSetAttribute(ballquery_kernel, cudaFuncAttributeMaxDynamicSharedMemorySize, smBq);
    cudaFuncSetAttribute(attn1_kernel,     cudaFuncAttributeMaxDynamicSharedMemorySize, smA1);

    mprep_kernel<<<2, 256>>>(w1q, w1k, w2q, w2k);
    fps_kernel<<<BB, 1024, smFps>>>(xyz, out);
    ballquery_kernel<<<dim3(NP / 8, BB), 256, smBq>>>(xyz);
    attn1_kernel<<<BB * NP, 256, smA1>>>(xyz, points, w1v, w1o, w1p, b1p);
    proj2_kernel<<<BB * 64, 256>>>(w2v, w2p, b2p);
    flash_kernel<<<dim3(NP / 32, BB), 256>>>();
    final_kernel<<<BB * 64, 256>>>(w2o, out2);
}

// round 5
// speedup vs baseline: 2.2965x; 1.5605x over previous
#include <cuda_runtime.h>
#include <math.h>
#include <stdint.h>

#define BB 8
#define NN 8192
#define NP 2048
#define NS 32
#define DINC 61
#define DD 64

typedef unsigned long long ull;
__device__ __forceinline__ ull pack2(float lo, float hi) {
    ull r; asm("mov.b64 %0, {%1,%2};" : "=l"(r) : "f"(lo), "f"(hi)); return r;
}
__device__ __forceinline__ float2 unpack2(ull v) {
    float2 r; asm("mov.b64 {%0,%1}, %2;" : "=f"(r.x), "=f"(r.y) : "l"(v)); return r;
}
__device__ __forceinline__ ull ffma2(ull a, ull b, ull c) {
    ull d; asm("fma.rn.f32x2 %0, %1, %2, %3;" : "=l"(d) : "l"(a), "l"(b), "l"(c)); return d;
}
__device__ __forceinline__ ull fadd2(ull a, ull b) {
    ull d; asm("add.rn.f32x2 %0, %1, %2;" : "=l"(d) : "l"(a), "l"(b)); return d;
}
__device__ __forceinline__ ull fmul2(ull a, ull b) {
    ull d; asm("mul.rn.f32x2 %0, %1, %2;" : "=l"(d) : "l"(a), "l"(b)); return d;
}

__device__ float g_newxyz[BB * NP * 3];
__device__ int   g_gi[BB * NP * NS];
__device__ float g_feat2[BB * NP * DD];
__device__ float g_qp[BB * NP * DD];
__device__ float g_v[BB * NP * DD];
__device__ float g_o[BB * NP * DD];
__device__ float g_M1[DD * DD];
__device__ float g_M2[DD * DD];

// ---------------- M = 0.125 * Wq @ Wk^T ----------------
__global__ void __launch_bounds__(256) mprep_kernel(
    const float* __restrict__ q1, const float* __restrict__ k1,
    const float* __restrict__ q2, const float* __restrict__ k2) {
    __shared__ float sq[4096], sk[4096];
    const float* q = blockIdx.x ? q2 : q1;
    const float* k = blockIdx.x ? k2 : k1;
    float* M = blockIdx.x ? g_M2 : g_M1;
    const int tid = threadIdx.x;
    for (int i = tid; i < 4096; i += 256) { sq[i] = q[i]; sk[i] = k[i]; }
    __syncthreads();
    for (int o = 0; o < 16; ++o) {
        const int idx = tid + o * 256;
        const int a = idx >> 6, c = idx & 63;
        float s = 0.f;
#pragma unroll 8
        for (int d = 0; d < 64; ++d) s += sq[a * 64 + d] * sk[c * 64 + d];
        M[idx] = 0.125f * s;
    }
}

// ---------------- FPS: packed f32x2 distances, 2 barriers/iter ----------------
__global__ void __launch_bounds__(1024) fps_kernel(const float* __restrict__ xyz,
                                                   float* __restrict__ out1) {
    extern __shared__ float sm[];
    float* sx   = sm;
    float* sy   = sm + NN;
    float* sz   = sm + 2 * NN;
    float* wmax = sm + 3 * NN;            // 32
    int*   sidx = (int*)(sm + 3 * NN + 32);  // 2 (double-buffered)

    const int b   = blockIdx.x;
    const int tid = threadIdx.x;
    const int lane = tid & 31, wid = tid >> 5;
    const float* xb = xyz + (size_t)b * 3 * NN;

    ull x2[4], y2[4], z2[4];
    float pd[8];
#pragma unroll
    for (int p = 0; p < 4; ++p) {
        const int i0 = tid + (2 * p) * 1024, i1 = i0 + 1024;
        const float xa = xb[i0], xbv = xb[i1];
        const float ya = xb[NN + i0], ybv = xb[NN + i1];
        const float za = xb[2 * NN + i0], zbv = xb[2 * NN + i1];
        x2[p] = pack2(xa, xbv); y2[p] = pack2(ya, ybv); z2[p] = pack2(za, zbv);
        sx[i0] = xa; sx[i1] = xbv; sy[i0] = ya; sy[i1] = ybv; sz[i0] = za; sz[i1] = zbv;
        pd[2 * p] = 1e10f; pd[2 * p + 1] = 1e10f;
    }
    if (tid == 0) sidx[0] = 0;
    __syncthreads();

    for (int it = 0; it < NP; ++it) {
        const int p = it & 1;
        const int cur = sidx[p];
        const float c0 = sx[cur], c1 = sy[cur], c2 = sz[cur];
        if (tid == 0) {
            g_newxyz[((size_t)b * NP + it) * 3 + 0] = c0;
            g_newxyz[((size_t)b * NP + it) * 3 + 1] = c1;
            g_newxyz[((size_t)b * NP + it) * 3 + 2] = c2;
            out1[(size_t)b * 3 * NP + it]          = c0;
            out1[(size_t)b * 3 * NP + NP + it]     = c1;
            out1[(size_t)b * 3 * NP + 2 * NP + it] = c2;
            sidx[p ^ 1] = 0x7fffffff;
        }
        // x + (-c) is IEEE-identical to x - c; f32x2 ops are componentwise RN,
        // so distances stay bit-exact vs the XLA elementwise lowering.
        const ull n0 = pack2(-c0, -c0), n1 = pack2(-c1, -c1), n2 = pack2(-c2, -c2);
        float tmax = -1.0f;
#pragma unroll
        for (int pp = 0; pp < 4; ++pp) {
            const ull dx = fadd2(x2[pp], n0);
            const ull dy = fadd2(y2[pp], n1);
            const ull dz = fadd2(z2[pp], n2);
            const ull d  = fadd2(fadd2(fmul2(dx, dx), fmul2(dy, dy)), fmul2(dz, dz));
            const float2 dv = unpack2(d);
            pd[2 * pp]     = fminf(pd[2 * pp], dv.x);
            pd[2 * pp + 1] = fminf(pd[2 * pp + 1], dv.y);
            tmax = fmaxf(tmax, fmaxf(pd[2 * pp], pd[2 * pp + 1]));
        }
        float wv = tmax;
#pragma unroll
        for (int off = 16; off; off >>= 1)
            wv = fmaxf(wv, __shfl_xor_sync(0xffffffffu, wv, off));
        if (lane == 0) wmax[wid] = wv;
        __syncthreads();
        float bm = wmax[lane];
#pragma unroll
        for (int off = 16; off; off >>= 1)
            bm = fmaxf(bm, __shfl_xor_sync(0xffffffffu, bm, off));
        if (tmax == bm) {
#pragma unroll
            for (int k = 0; k < 8; ++k)
                if (pd[k] == bm) atomicMin(&sidx[p ^ 1], tid + k * 1024);
        }
        __syncthreads();
    }
}

// ---------------- ball query (unchanged, decision-exact) ----------------
__global__ void __launch_bounds__(256) ballquery_kernel(const float* __restrict__ xyz) {
    extern __shared__ float sm[];
    float* sx = sm;
    float* sy = sm + NN;
    float* sz = sm + 2 * NN;

    const int b   = blockIdx.y;
    const int tid = threadIdx.x;
    const float* xb = xyz + (size_t)b * 3 * NN;
    for (int i = tid; i < NN; i += 256) {
        sx[i] = xb[i]; sy[i] = xb[NN + i]; sz[i] = xb[2 * NN + i];
    }
    __syncthreads();

    const int wid = tid >> 5, lane = tid & 31;
    const int s = blockIdx.x * 8 + wid;
    const float r2 = (float)(0.2 * 0.2);

    const float c0 = g_newxyz[((size_t)b * NP + s) * 3 + 0];
    const float c1 = g_newxyz[((size_t)b * NP + s) * 3 + 1];
    const float c2 = g_newxyz[((size_t)b * NP + s) * 3 + 2];
    const float sqc = __fadd_rn(__fadd_rn(__fmul_rn(c0, c0), __fmul_rn(c1, c1)),
                                __fmul_rn(c2, c2));
    const size_t gbase = ((size_t)b * NP + s) * NS;

    int count = 0;
    int firstIdx = -1;
    for (int base = 0; base < NN && count < NS; base += 32) {
        const int i = base + lane;
        const float x = sx[i], y = sy[i], z = sz[i];
        const float sqx = __fadd_rn(__fadd_rn(__fmul_rn(x, x), __fmul_rn(y, y)),
                                    __fmul_rn(z, z));
        const float cx = fmaf(c2, z, fmaf(c1, y, __fmul_rn(c0, x)));
        const float sqr = __fsub_rn(__fadd_rn(sqc, sqx), __fmul_rn(2.0f, cx));
        const bool hit = !(sqr > r2);
        const unsigned mask = __ballot_sync(0xffffffffu, hit);
        if (firstIdx < 0 && mask) firstIdx = base + __ffs(mask) - 1;
        if (hit) {
            int slot = count + __popc(mask & ((1u << lane) - 1u));
            if (slot < NS) g_gi[gbase + slot] = i;
        }
        count += __popc(mask);
    }
    int cnt = count < NS ? count : NS;
    for (int j = cnt + lane; j < NS; j += 32) g_gi[gbase + j] = firstIdx;
}

// ---------------- attn1: weights via LDG(L1), 2 rows/thread, f32x2 ----------------
// smem floats: ft 0(2176) | ftT 2176(2304, reused as om) | tm 4480(2176) |
//              vm 6656(2176) | sc 8832(1152) | px/py/pz 9984(96) | red 10080(512) |
//              sidx 10592(32 int) ; padded to 58880 bytes to pin 3 blocks/SM.
#define A1_SMEM_BYTES 58880

__global__ void __launch_bounds__(256) attn1_kernel(
    const float* __restrict__ xyz, const float* __restrict__ points,
    const float* __restrict__ wv, const float* __restrict__ wo,
    const float* __restrict__ wp, const float* __restrict__ bp) {
    extern __shared__ float sm[];
    float* ft  = sm;
    float* ftT = sm + 2176;
    float* tm  = sm + 4480;
    float* vm  = sm + 6656;
    float* sc  = sm + 8832;
    float* px  = sm + 9984;
    float* py  = sm + 10016;
    float* pz  = sm + 10048;
    float* red = sm + 10080;
    int* sidx  = (int*)(sm + 10592);
    float* om  = ftT;   // reuse after score phase

    const int g   = blockIdx.x;
    const int b   = g >> 11;
    const int tid = threadIdx.x;
    const int lane = tid & 31, wid = tid >> 5;

    if (tid < 32) {
        const int id = g_gi[(size_t)g * NS + tid];
        sidx[tid] = id;
        const float c0 = g_newxyz[(size_t)g * 3 + 0];
        const float c1 = g_newxyz[(size_t)g * 3 + 1];
        const float c2 = g_newxyz[(size_t)g * 3 + 2];
        const float X = xyz[(size_t)b * 3 * NN + id];
        const float Y = xyz[(size_t)b * 3 * NN + NN + id];
        const float Z = xyz[(size_t)b * 3 * NN + 2 * NN + id];
        px[tid] = X; py[tid] = Y; pz[tid] = Z;
        ft[tid * 68 + 0] = X - c0;
        ft[tid * 68 + 1] = Y - c1;
        ft[tid * 68 + 2] = Z - c2;
    }
    __syncthreads();
    for (int i = tid; i < NS * DINC; i += 256) {
        const int c = i >> 5, j = i & 31;
        ft[j * 68 + 3 + c] = points[(size_t)b * DINC * NN + (size_t)c * NN + sidx[j]];
    }
    __syncthreads();

    const int th = tid & 15;     // d-slice
    const int d0 = th * 4;
    const int t  = tid >> 4;     // rows t and t+16

    {   // tm = ft@Ms ; vm = ft@Wv + pos + bias (weights via LDG/L1)
        ull at0 = 0, at1 = 0, bt0 = 0, bt1 = 0;
        ull av0 = 0, av1 = 0, bv0 = 0, bv1 = 0;
        const float* fr0 = ft + t * 68;
        const float* fr1 = ft + (t + 16) * 68;
        const float* mp = g_M1 + d0;
        const float* vp = wv + d0;
#pragma unroll 8
        for (int e = 0; e < 64; ++e) {
            const float f0 = fr0[e], f1 = fr1[e];
            const ull f02 = pack2(f0, f0), f12 = pack2(f1, f1);
            const ulonglong2 m = *(const ulonglong2*)(mp + e * 64);
            const ulonglong2 v = *(const ulonglong2*)(vp + e * 64);
            at0 = ffma2(f02, m.x, at0); at1 = ffma2(f02, m.y, at1);
            bt0 = ffma2(f12, m.x, bt0); bt1 = ffma2(f12, m.y, bt1);
            av0 = ffma2(f02, v.x, av0); av1 = ffma2(f02, v.y, av1);
            bv0 = ffma2(f12, v.x, bv0); bv1 = ffma2(f12, v.y, bv1);
        }
        const ulonglong2 wx = *(const ulonglong2*)(wp + d0);
        const ulonglong2 wy = *(const ulonglong2*)(wp + 64 + d0);
        const ulonglong2 wz = *(const ulonglong2*)(wp + 128 + d0);
        const ulonglong2 wb = *(const ulonglong2*)(bp + d0);
        const ull X0 = pack2(px[t], px[t]), Y0 = pack2(py[t], py[t]), Z0 = pack2(pz[t], pz[t]);
        const ull X1 = pack2(px[t + 16], px[t + 16]), Y1 = pack2(py[t + 16], py[t + 16]),
                  Z1 = pack2(pz[t + 16], pz[t + 16]);
        av0 = ffma2(X0, wx.x, av0); av1 = ffma2(X0, wx.y, av1);
        av0 = ffma2(Y0, wy.x, av0); av1 = ffma2(Y0, wy.y, av1);
        av0 = ffma2(Z0, wz.x, av0); av1 = ffma2(Z0, wz.y, av1);
        av0 = fadd2(av0, wb.x);     av1 = fadd2(av1, wb.y);
        bv0 = ffma2(X1, wx.x, bv0); bv1 = ffma2(X1, wx.y, bv1);
        bv0 = ffma2(Y1, wy.x, bv0); bv1 = ffma2(Y1, wy.y, bv1);
        bv0 = ffma2(Z1, wz.x, bv0); bv1 = ffma2(Z1, wz.y, bv1);
        bv0 = fadd2(bv0, wb.x);     bv1 = fadd2(bv1, wb.y);
        *(ull*)&tm[t * 68 + d0]            = at0;
        *(ull*)&tm[t * 68 + d0 + 2]        = at1;
        *(ull*)&tm[(t + 16) * 68 + d0]     = bt0;
        *(ull*)&tm[(t + 16) * 68 + d0 + 2] = bt1;
        *(ull*)&vm[t * 68 + d0]            = av0;
        *(ull*)&vm[t * 68 + d0 + 2]        = av1;
        *(ull*)&vm[(t + 16) * 68 + d0]     = bv0;
        *(ull*)&vm[(t + 16) * 68 + d0 + 2] = bv1;
    }
#pragma unroll
    for (int r = 0; r < 8; ++r) {   // ft -> ftT transpose
        const int idx = tid + r * 256;
        const int e = idx >> 5, j = idx & 31;
        ftT[e * 36 + j] = ft[j * 68 + e];
    }
    __syncthreads();

    {   // scores: rows t & t+16, 2 keys per thread (packed)
        const int j0 = th * 2;
        ull sA = 0, sB = 0;
        const float* trA = tm + t * 68;
        const float* trB = tm + (t + 16) * 68;
#pragma unroll 8
        for (int e = 0; e < 64; ++e) {
            const ull fj = *(const ull*)&ftT[e * 36 + j0];
            sA = ffma2(pack2(trA[e], trA[e]), fj, sA);
            sB = ffma2(pack2(trB[e], trB[e]), fj, sB);
        }
        *(ull*)&sc[t * 36 + j0]        = sA;
        *(ull*)&sc[(t + 16) * 36 + j0] = sB;
    }
    __syncthreads();

    for (int rep = 0; rep < 4; ++rep) {   // softmax rows (warp per row)
        const int r = wid * 4 + rep;
        float v = sc[r * 36 + lane];
        float mx = v;
#pragma unroll
        for (int off = 16; off; off >>= 1)
            mx = fmaxf(mx, __shfl_xor_sync(0xffffffffu, mx, off));
        const float pe = __expf(v - mx);
        float ssum = pe;
#pragma unroll
        for (int off = 16; off; off >>= 1)
            ssum += __shfl_xor_sync(0xffffffffu, ssum, off);
        sc[r * 36 + lane] = pe * __fdividef(1.0f, ssum);
    }
    __syncthreads();

    {   // om = p @ vm (rows t, t+16)
        ull oA0 = 0, oA1 = 0, oB0 = 0, oB1 = 0;
        const float* pA = sc + t * 36;
        const float* pB = sc + (t + 16) * 36;
#pragma unroll 4
        for (int j = 0; j < 32; ++j) {
            const ull p0 = pack2(pA[j], pA[j]);
            const ull p1 = pack2(pB[j], pB[j]);
            const ulonglong2 v = *(const ulonglong2*)&vm[j * 68 + d0];
            oA0 = ffma2(p0, v.x, oA0); oA1 = ffma2(p0, v.y, oA1);
            oB0 = ffma2(p1, v.x, oB0); oB1 = ffma2(p1, v.y, oB1);
        }
        *(ull*)&om[t * 68 + d0]            = oA0;
        *(ull*)&om[t * 68 + d0 + 2]        = oA1;
        *(ull*)&om[(t + 16) * 68 + d0]     = oB0;
        *(ull*)&om[(t + 16) * 68 + d0 + 2] = oB1;
    }
    __syncthreads();

    {   // z = ft + om @ Wo, max over rows
        ull zA0, zA1, zB0, zB1;
        {
            const ulonglong2 fA = *(const ulonglong2*)&ft[t * 68 + d0];
            const ulonglong2 fB = *(const ulonglong2*)&ft[(t + 16) * 68 + d0];
            zA0 = fA.x; zA1 = fA.y; zB0 = fB.x; zB1 = fB.y;
        }
        const float* oA = om + t * 68;
        const float* oB = om + (t + 16) * 68;
        const float* wop = wo + d0;
#pragma unroll 8
        for (int e = 0; e < 64; ++e) {
            const ulonglong2 w = *(const ulonglong2*)(wop + e * 64);
            const ull a2 = pack2(oA[e], oA[e]);
            const ull b2 = pack2(oB[e], oB[e]);
            zA0 = ffma2(a2, w.x, zA0); zA1 = ffma2(a2, w.y, zA1);
            zB0 = ffma2(b2, w.x, zB0); zB1 = ffma2(b2, w.y, zB1);
        }
        const float2 a0 = unpack2(zA0), a1 = unpack2(zA1);
        const float2 b0 = unpack2(zB0), b1 = unpack2(zB1);
        float z0 = fmaxf(a0.x, b0.x), z1 = fmaxf(a0.y, b0.y);
        float z2 = fmaxf(a1.x, b1.x), z3 = fmaxf(a1.y, b1.y);
        z0 = fmaxf(z0, __shfl_xor_sync(0xffffffffu, z0, 16));
        z1 = fmaxf(z1, __shfl_xor_sync(0xffffffffu, z1, 16));
        z2 = fmaxf(z2, __shfl_xor_sync(0xffffffffu, z2, 16));
        z3 = fmaxf(z3, __shfl_xor_sync(0xffffffffu, z3, 16));
        if (lane < 16) *(float4*)&red[wid * 64 + d0] = make_float4(z0, z1, z2, z3);
    }
    __syncthreads();
    if (tid < 64) {
        float m = red[tid];
#pragma unroll
        for (int w = 1; w < 8; ++w) m = fmaxf(m, red[w * 64 + tid]);
        g_feat2[(size_t)g * 64 + tid] = m;
    }
}

// ---------------- proj2 (unchanged from R4) ----------------
__global__ void __launch_bounds__(256) proj2_kernel(
    const float* __restrict__ wv2, const float* __restrict__ wp2,
    const float* __restrict__ bp2) {
    __shared__ float ft2[32 * 68];
    __shared__ float Ms[4096], Wv[4096], Wp[192], Bp[64];
    __shared__ float px[32], py[32], pz[32];

    const int b  = blockIdx.x >> 6;
    const int t0 = (blockIdx.x & 63) * 32;
    const int tid = threadIdx.x;

    for (int i = tid; i < 4096; i += 256) { Ms[i] = g_M2[i]; Wv[i] = wv2[i]; }
    if (tid < 192) Wp[tid] = wp2[tid];
    if (tid < 64)  Bp[tid] = bp2[tid];
#pragma unroll
    for (int r = 0; r < 2; ++r) {
        const int f4 = tid + r * 256;
        const int tt = f4 >> 4, c4 = (f4 & 15) * 4;
        *(float4*)&ft2[tt * 68 + c4] =
            *(const float4*)&g_feat2[((size_t)(b * NP + t0 + tt)) * 64 + c4];
    }
    if (tid < 32) {
        px[tid] = g_newxyz[((size_t)(b * NP + t0 + tid)) * 3 + 0];
        py[tid] = g_newxyz[((size_t)(b * NP + t0 + tid)) * 3 + 1];
        pz[tid] = g_newxyz[((size_t)(b * NP + t0 + tid)) * 3 + 2];
    }
    __syncthreads();

    const int t  = tid >> 3;
    const int d0 = (tid & 7) * 8;
    float aq[8] = {0,0,0,0,0,0,0,0};
    float av[8] = {0,0,0,0,0,0,0,0};
    const float* fr = ft2 + t * 68;
#pragma unroll 4
    for (int e = 0; e < 64; ++e) {
        const float f = fr[e];
        const float4 m0 = *(const float4*)&Ms[e * 64 + d0];
        const float4 m1 = *(const float4*)&Ms[e * 64 + d0 + 4];
        const float4 v0 = *(const float4*)&Wv[e * 64 + d0];
        const float4 v1 = *(const float4*)&Wv[e * 64 + d0 + 4];
        aq[0] += f * m0.x; aq[1] += f * m0.y; aq[2] += f * m0.z; aq[3] += f * m0.w;
        aq[4] += f * m1.x; aq[5] += f * m1.y; aq[6] += f * m1.z; aq[7] += f * m1.w;
        av[0] += f * v0.x; av[1] += f * v0.y; av[2] += f * v0.z; av[3] += f * v0.w;
        av[4] += f * v1.x; av[5] += f * v1.y; av[6] += f * v1.z; av[7] += f * v1.w;
    }
    const float X = px[t], Y = py[t], Z = pz[t];
#pragma unroll
    for (int i = 0; i < 8; ++i)
        av[i] += X * Wp[d0 + i] + Y * Wp[64 + d0 + i] + Z * Wp[128 + d0 + i] + Bp[d0 + i];

    const size_t o = ((size_t)(b * NP + t0 + t)) * 64 + d0;
    *(float4*)&g_qp[o]     = make_float4(aq[0], aq[1], aq[2], aq[3]);
    *(float4*)&g_qp[o + 4] = make_float4(aq[4], aq[5], aq[6], aq[7]);
    *(float4*)&g_v[o]      = make_float4(av[0], av[1], av[2], av[3]);
    *(float4*)&g_v[o + 4]  = make_float4(av[4], av[5], av[6], av[7]);
}

// ---------------- attn2 flash: packed scores ----------------
__global__ void __launch_bounds__(256) flash_kernel() {
    __shared__ float qs[32 * 68];
    __shared__ float ks[32 * 68];
    __shared__ float vs[32 * 68];
    __shared__ float ps[8 * 144];

    const int b   = blockIdx.y;
    const int q0  = blockIdx.x * 32;
    const int tid = threadIdx.x;
    const int lane = tid & 31, wid = tid >> 5;

#pragma unroll
    for (int r = 0; r < 2; ++r) {
        const int f4 = tid + r * 256;
        const int tt = f4 >> 4, c4 = (f4 & 15) * 4;
        *(float4*)&qs[tt * 68 + c4] =
            *(const float4*)&g_qp[((size_t)(b * NP + q0 + tt)) * 64 + c4];
    }

    float m0q = -1e30f, m1q = -1e30f, m2q = -1e30f, m3q = -1e30f;
    float l0 = 0.f, l1 = 0.f, l2 = 0.f, l3 = 0.f;
    float oa0 = 0.f, oa1 = 0.f, oa2 = 0.f, oa3 = 0.f;
    float ob0 = 0.f, ob1 = 0.f, ob2 = 0.f, ob3 = 0.f;

    const float* q0r = qs + (wid * 4 + 0) * 68;
    const float* q1r = qs + (wid * 4 + 1) * 68;
    const float* q2r = qs + (wid * 4 + 2) * 68;
    const float* q3r = qs + (wid * 4 + 3) * 68;
    float* pw = ps + wid * 144;

    for (int c = 0; c < NP / 32; ++c) {
        __syncthreads();
        const int kb = b * NP + c * 32;
#pragma unroll
        for (int r = 0; r < 2; ++r) {
            const int f4 = tid + r * 256;
            const int tt = f4 >> 4, c4 = (f4 & 15) * 4;
            *(float4*)&ks[tt * 68 + c4] =
                *(const float4*)&g_feat2[((size_t)(kb + tt)) * 64 + c4];
            *(float4*)&vs[tt * 68 + c4] =
                *(const float4*)&g_v[((size_t)(kb + tt)) * 64 + c4];
        }
        __syncthreads();

        ull sp0 = 0, sp1 = 0, sp2 = 0, sp3 = 0;
        const float* krow = ks + lane * 68;
#pragma unroll
        for (int e4 = 0; e4 < 16; ++e4) {
            const ulonglong2 k4 = *(const ulonglong2*)&krow[e4 * 4];
            ulonglong2 a;
            a = *(const ulonglong2*)&q0r[e4 * 4];
            sp0 = ffma2(a.x, k4.x, sp0); sp0 = ffma2(a.y, k4.y, sp0);
            a = *(const ulonglong2*)&q1r[e4 * 4];
            sp1 = ffma2(a.x, k4.x, sp1); sp1 = ffma2(a.y, k4.y, sp1);
            a = *(const ulonglong2*)&q2r[e4 * 4];
            sp2 = ffma2(a.x, k4.x, sp2); sp2 = ffma2(a.y, k4.y, sp2);
            a = *(const ulonglong2*)&q3r[e4 * 4];
            sp3 = ffma2(a.x, k4.x, sp3); sp3 = ffma2(a.y, k4.y, sp3);
        }
        const float2 u0 = unpack2(sp0), u1 = unpack2(sp1);
        const float2 u2 = unpack2(sp2), u3 = unpack2(sp3);
        float s0 = u0.x + u0.y, s1 = u1.x + u1.y, s2 = u2.x + u2.y, s3 = u3.x + u3.y;

#define FLASH_SM(S, M, L, OA, OB, QQ)                                        \
        {                                                                    \
            float cm = S;                                                    \
            cm = fmaxf(cm, __shfl_xor_sync(0xffffffffu, cm, 16));            \
            cm = fmaxf(cm, __shfl_xor_sync(0xffffffffu, cm, 8));             \
            cm = fmaxf(cm, __shfl_xor_sync(0xffffffffu, cm, 4));             \
            cm = fmaxf(cm, __shfl_xor_sync(0xffffffffu, cm, 2));             \
            cm = fmaxf(cm, __shfl_xor_sync(0xffffffffu, cm, 1));             \
            const float mn = fmaxf(M, cm);                                   \
            const float corr = __expf(M - mn);                               \
            const float pe = __expf(S - mn);                                 \
            float sp = pe;                                                   \
            sp += __shfl_xor_sync(0xffffffffu, sp, 16);                      \
            sp += __shfl_xor_sync(0xffffffffu, sp, 8);                       \
            sp += __shfl_xor_sync(0xffffffffu, sp, 4);                       \
            sp += __shfl_xor_sync(0xffffffffu, sp, 2);                       \
            sp += __shfl_xor_sync(0xffffffffu, sp, 1);                       \
            L = L * corr + sp;                                               \
            OA *= corr; OB *= corr;                                          \
            pw[QQ * 36 + lane] = pe;                                         \
            M = mn;                                                          \
        }
        FLASH_SM(s0, m0q, l0, oa0, ob0, 0)
        FLASH_SM(s1, m1q, l1, oa1, ob1, 1)
        FLASH_SM(s2, m2q, l2, oa2, ob2, 2)
        FLASH_SM(s3, m3q, l3, oa3, ob3, 3)
#undef FLASH_SM
        __syncwarp();

#pragma unroll
        for (int j4 = 0; j4 < 8; ++j4) {
            float pa0[4], pa1[4], pa2[4], pa3[4];
            *(float4*)pa0 = *(const float4*)&pw[0   + j4 * 4];
            *(float4*)pa1 = *(const float4*)&pw[36  + j4 * 4];
            *(float4*)pa2 = *(const float4*)&pw[72  + j4 * 4];
            *(float4*)pa3 = *(const float4*)&pw[108 + j4 * 4];
#pragma unroll
            for (int jj = 0; jj < 4; ++jj) {
                const int j = j4 * 4 + jj;
                const float va = vs[j * 68 + lane];
                const float vb = vs[j * 68 + 32 + lane];
                oa0 += pa0[jj] * va; ob0 += pa0[jj] * vb;
                oa1 += pa1[jj] * va; ob1 += pa1[jj] * vb;
                oa2 += pa2[jj] * va; ob2 += pa2[jj] * vb;
                oa3 += pa3[jj] * va; ob3 += pa3[jj] * vb;
            }
        }
        __syncwarp();
    }

    const size_t ob = ((size_t)(b * NP + q0 + wid * 4)) * 64;
    g_o[ob + lane]       = oa0 / l0;
    g_o[ob + 32 + lane]  = ob0 / l0;
    g_o[ob + 64 + lane]  = oa1 / l1;
    g_o[ob + 96 + lane]  = ob1 / l1;
    g_o[ob + 128 + lane] = oa2 / l2;
    g_o[ob + 160 + lane] = ob2 / l2;
    g_o[ob + 192 + lane] = oa3 / l3;
    g_o[ob + 224 + lane] = ob3 / l3;
}

// ---------------- final (unchanged from R4) ----------------
__global__ void __launch_bounds__(256) final_kernel(const float* __restrict__ wo,
                                                    float* __restrict__ out2) {
    __shared__ float ot[32 * 68];
    __shared__ float Wo[4096];
    __shared__ float zs[32 * 68];

    const int b  = blockIdx.x >> 6;
    const int t0 = (blockIdx.x & 63) * 32;
    const int tid = threadIdx.x;

    for (int i = tid; i < 4096; i += 256) Wo[i] = wo[i];
#pragma unroll
    for (int r = 0; r < 2; ++r) {
        const int f4 = tid + r * 256;
        const int tt = f4 >> 4, c4 = (f4 & 15) * 4;
        *(float4*)&ot[tt * 68 + c4] =
            *(const float4*)&g_o[((size_t)(b * NP + t0 + tt)) * 64 + c4];
    }
    __syncthreads();

    const int t  = tid >> 3;
    const int d0 = (tid & 7) * 8;
    float z[8];
    {
        const size_t fo = ((size_t)(b * NP + t0 + t)) * 64 + d0;
        const float4 f0 = *(const float4*)&g_feat2[fo];
        const float4 f1 = *(const float4*)&g_feat2[fo + 4];
        z[0] = f0.x; z[1] = f0.y; z[2] = f0.z; z[3] = f0.w;
        z[4] = f1.x; z[5] = f1.y; z[6] = f1.z; z[7] = f1.w;
    }
    const float* orow = ot + t * 68;
#pragma unroll 4
    for (int e = 0; e < 64; ++e) {
        const float a = orow[e];
        const float4 w0 = *(const float4*)&Wo[e * 64 + d0];
        const float4 w1 = *(const float4*)&Wo[e * 64 + d0 + 4];
        z[0] += a * w0.x; z[1] += a * w0.y; z[2] += a * w0.z; z[3] += a * w0.w;
        z[4] += a * w1.x; z[5] += a * w1.y; z[6] += a * w1.z; z[7] += a * w1.w;
    }
    *(float4*)&zs[t * 68 + d0]     = make_float4(z[0], z[1], z[2], z[3]);
    *(float4*)&zs[t * 68 + d0 + 4] = make_float4(z[4], z[5], z[6], z[7]);
    __syncthreads();

    for (int i = tid; i < 2048; i += 256) {
        const int d = i >> 5, tt = i & 31;
        out2[(size_t)b * DD * NP + (size_t)d * NP + t0 + tt] = zs[tt * 68 + d];
    }
}

// ---------------- launch ----------------
extern "C" void kernel_launch(void* const* d_in, const int* in_sizes, int n_in,
                              void* d_out, int out_size) {
    const float* xyz    = (const float*)d_in[0];
    const float* points = (const float*)d_in[1];
    const float* w1q = (const float*)d_in[2];
    const float* w1k = (const float*)d_in[3];
    const float* w1v = (const float*)d_in[4];
    const float* w1o = (const float*)d_in[5];
    const float* w1p = (const float*)d_in[6];
    const float* b1p = (const float*)d_in[7];
    const float* w2q = (const float*)d_in[8];
    const float* w2k = (const float*)d_in[9];
    const float* w2v = (const float*)d_in[10];
    const float* w2o = (const float*)d_in[11];
    const float* w2p = (const float*)d_in[12];
    const float* b2p = (const float*)d_in[13];

    float* out  = (float*)d_out;
    float* out2 = out + (size_t)BB * 3 * NP;

    const int smFps = (3 * NN + 32) * 4 + 8;
    const int smBq  = 3 * NN * 4;

    cudaFuncSetAttribute(fps_kernel,       cudaFuncAttributeMaxDynamicSharedMemorySize, smFps);
    cudaFuncSetAttribute(ballquery_kernel, cudaFuncAttributeMaxDynamicSharedMemorySize, smBq);
    cudaFuncSetAttribute(attn1_kernel,     cudaFuncAttributeMaxDynamicSharedMemorySize, A1_SMEM_BYTES);

    mprep_kernel<<<2, 256>>>(w1q, w1k, w2q, w2k);
    fps_kernel<<<BB, 1024, smFps>>>(xyz, out);
    ballquery_kernel<<<dim3(NP / 8, BB), 256, smBq>>>(xyz);
    attn1_kernel<<<BB * NP, 256, A1_SMEM_BYTES>>>(xyz, points, w1v, w1o, w1p, b1p);
    proj2_kernel<<<BB * 64, 256>>>(w2v, w2p, b2p);
    flash_kernel<<<dim3(NP / 32, BB), 256>>>();
    final_kernel<<<BB * 64, 256>>>(w2o, out2);
}

// round 7
// speedup vs baseline: 2.4459x; 1.0651x over previous
#include <cuda_runtime.h>
#include <math.h>
#include <stdint.h>

#define BB 8
#define NN 8192
#define NP 2048
#define NS 32
#define DINC 61
#define DD 64

typedef unsigned long long ull;
__device__ __forceinline__ ull pack2(float lo, float hi) {
    ull r; asm("mov.b64 %0, {%1,%2};" : "=l"(r) : "f"(lo), "f"(hi)); return r;
}
__device__ __forceinline__ float2 unpack2(ull v) {
    float2 r; asm("mov.b64 {%0,%1}, %2;" : "=f"(r.x), "=f"(r.y) : "l"(v)); return r;
}
__device__ __forceinline__ ull ffma2(ull a, ull b, ull c) {
    ull d; asm("fma.rn.f32x2 %0, %1, %2, %3;" : "=l"(d) : "l"(a), "l"(b), "l"(c)); return d;
}
__device__ __forceinline__ ull fadd2(ull a, ull b) {
    ull d; asm("add.rn.f32x2 %0, %1, %2;" : "=l"(d) : "l"(a), "l"(b)); return d;
}
__device__ __forceinline__ ull fmul2(ull a, ull b) {
    ull d; asm("mul.rn.f32x2 %0, %1, %2;" : "=l"(d) : "l"(a), "l"(b)); return d;
}

__device__ float g_newxyz[BB * NP * 3];
__device__ int   g_gi[BB * NP * NS];
__device__ float g_feat2[BB * NP * DD];
__device__ float g_qp[BB * NP * DD];
__device__ float g_v[BB * NP * DD];
__device__ float g_o[BB * NP * DD];
__device__ float g_M1[DD * DD];
__device__ float g_M2[DD * DD];

// ---------------- M = 0.125 * Wq @ Wk^T ----------------
__global__ void __launch_bounds__(256) mprep_kernel(
    const float* __restrict__ q1, const float* __restrict__ k1,
    const float* __restrict__ q2, const float* __restrict__ k2) {
    __shared__ float sq[4096], sk[4096];
    const float* q = blockIdx.x ? q2 : q1;
    const float* k = blockIdx.x ? k2 : k1;
    float* M = blockIdx.x ? g_M2 : g_M1;
    const int tid = threadIdx.x;
    for (int i = tid; i < 4096; i += 256) { sq[i] = q[i]; sk[i] = k[i]; }
    __syncthreads();
    for (int o = 0; o < 16; ++o) {
        const int idx = tid + o * 256;
        const int a = idx >> 6, c = idx & 63;
        float s = 0.f;
#pragma unroll 8
        for (int d = 0; d < 64; ++d) s += sq[a * 64 + d] * sk[c * 64 + d];
        M[idx] = 0.125f * s;
    }
}

// ---------------- FPS (unchanged from R5: bit-exact, packed f32x2) ----------------
__global__ void __launch_bounds__(1024) fps_kernel(const float* __restrict__ xyz,
                                                   float* __restrict__ out1) {
    extern __shared__ float sm[];
    float* sx   = sm;
    float* sy   = sm + NN;
    float* sz   = sm + 2 * NN;
    float* wmax = sm + 3 * NN;
    int*   sidx = (int*)(sm + 3 * NN + 32);

    const int b   = blockIdx.x;
    const int tid = threadIdx.x;
    const int lane = tid & 31, wid = tid >> 5;
    const float* xb = xyz + (size_t)b * 3 * NN;

    ull x2[4], y2[4], z2[4];
    float pd[8];
#pragma unroll
    for (int p = 0; p < 4; ++p) {
        const int i0 = tid + (2 * p) * 1024, i1 = i0 + 1024;
        const float xa = xb[i0], xbv = xb[i1];
        const float ya = xb[NN + i0], ybv = xb[NN + i1];
        const float za = xb[2 * NN + i0], zbv = xb[2 * NN + i1];
        x2[p] = pack2(xa, xbv); y2[p] = pack2(ya, ybv); z2[p] = pack2(za, zbv);
        sx[i0] = xa; sx[i1] = xbv; sy[i0] = ya; sy[i1] = ybv; sz[i0] = za; sz[i1] = zbv;
        pd[2 * p] = 1e10f; pd[2 * p + 1] = 1e10f;
    }
    if (tid == 0) sidx[0] = 0;
    __syncthreads();

    for (int it = 0; it < NP; ++it) {
        const int p = it & 1;
        const int cur = sidx[p];
        const float c0 = sx[cur], c1 = sy[cur], c2 = sz[cur];
        if (tid == 0) {
            g_newxyz[((size_t)b * NP + it) * 3 + 0] = c0;
            g_newxyz[((size_t)b * NP + it) * 3 + 1] = c1;
            g_newxyz[((size_t)b * NP + it) * 3 + 2] = c2;
            out1[(size_t)b * 3 * NP + it]          = c0;
            out1[(size_t)b * 3 * NP + NP + it]     = c1;
            out1[(size_t)b * 3 * NP + 2 * NP + it] = c2;
            sidx[p ^ 1] = 0x7fffffff;
        }
        const ull n0 = pack2(-c0, -c0), n1 = pack2(-c1, -c1), n2 = pack2(-c2, -c2);
        float tmax = -1.0f;
#pragma unroll
        for (int pp = 0; pp < 4; ++pp) {
            const ull dx = fadd2(x2[pp], n0);
            const ull dy = fadd2(y2[pp], n1);
            const ull dz = fadd2(z2[pp], n2);
            const ull d  = fadd2(fadd2(fmul2(dx, dx), fmul2(dy, dy)), fmul2(dz, dz));
            const float2 dv = unpack2(d);
            pd[2 * pp]     = fminf(pd[2 * pp], dv.x);
            pd[2 * pp + 1] = fminf(pd[2 * pp + 1], dv.y);
            tmax = fmaxf(tmax, fmaxf(pd[2 * pp], pd[2 * pp + 1]));
        }
        float wv = tmax;
#pragma unroll
        for (int off = 16; off; off >>= 1)
            wv = fmaxf(wv, __shfl_xor_sync(0xffffffffu, wv, off));
        if (lane == 0) wmax[wid] = wv;
        __syncthreads();
        float bm = wmax[lane];
#pragma unroll
        for (int off = 16; off; off >>= 1)
            bm = fmaxf(bm, __shfl_xor_sync(0xffffffffu, bm, off));
        if (tmax == bm) {
#pragma unroll
            for (int k = 0; k < 8; ++k)
                if (pd[k] == bm) atomicMin(&sidx[p ^ 1], tid + k * 1024);
        }
        __syncthreads();
    }
}

// ---------------- ball query (unchanged, decision-exact) ----------------
__global__ void __launch_bounds__(256) ballquery_kernel(const float* __restrict__ xyz) {
    extern __shared__ float sm[];
    float* sx = sm;
    float* sy = sm + NN;
    float* sz = sm + 2 * NN;

    const int b   = blockIdx.y;
    const int tid = threadIdx.x;
    const float* xb = xyz + (size_t)b * 3 * NN;
    for (int i = tid; i < NN; i += 256) {
        sx[i] = xb[i]; sy[i] = xb[NN + i]; sz[i] = xb[2 * NN + i];
    }
    __syncthreads();

    const int wid = tid >> 5, lane = tid & 31;
    const int s = blockIdx.x * 8 + wid;
    const float r2 = (float)(0.2 * 0.2);

    const float c0 = g_newxyz[((size_t)b * NP + s) * 3 + 0];
    const float c1 = g_newxyz[((size_t)b * NP + s) * 3 + 1];
    const float c2 = g_newxyz[((size_t)b * NP + s) * 3 + 2];
    const float sqc = __fadd_rn(__fadd_rn(__fmul_rn(c0, c0), __fmul_rn(c1, c1)),
                                __fmul_rn(c2, c2));
    const size_t gbase = ((size_t)b * NP + s) * NS;

    int count = 0;
    int firstIdx = -1;
    for (int base = 0; base < NN && count < NS; base += 32) {
        const int i = base + lane;
        const float x = sx[i], y = sy[i], z = sz[i];
        const float sqx = __fadd_rn(__fadd_rn(__fmul_rn(x, x), __fmul_rn(y, y)),
                                    __fmul_rn(z, z));
        const float cx = fmaf(c2, z, fmaf(c1, y, __fmul_rn(c0, x)));
        const float sqr = __fsub_rn(__fadd_rn(sqc, sqx), __fmul_rn(2.0f, cx));
        const bool hit = !(sqr > r2);
        const unsigned mask = __ballot_sync(0xffffffffu, hit);
        if (firstIdx < 0 && mask) firstIdx = base + __ffs(mask) - 1;
        if (hit) {
            int slot = count + __popc(mask & ((1u << lane) - 1u));
            if (slot < NS) g_gi[gbase + slot] = i;
        }
        count += __popc(mask);
    }
    int cnt = count < NS ? count : NS;
    for (int j = cnt + lane; j < NS; j += 32) g_gi[gbase + j] = firstIdx;
}

// ---------------- attn1: R=4 rows/thread on weight-bound phases ----------------
// smem floats: ft 0(2176) | ftT 2176(2304, reused as om) | tm 4480(2176) |
//              vm 6656(2176) | sc 8832(1152) | px/py/pz 9984(96) | red 10080(512) |
//              sidx 10592(32 int) = 42496 B, padded to 43008 (4 blocks/SM).
#define A1_SMEM_BYTES 43008

__global__ void __launch_bounds__(256, 4) attn1_kernel(
    const float* __restrict__ xyz, const float* __restrict__ points,
    const float* __restrict__ wv, const float* __restrict__ wo,
    const float* __restrict__ wp, const float* __restrict__ bp) {
    extern __shared__ float sm[];
    float* ft  = sm;
    float* ftT = sm + 2176;
    float* tm  = sm + 4480;
    float* vm  = sm + 6656;
    float* sc  = sm + 8832;
    float* px  = sm + 9984;
    float* py  = sm + 10016;
    float* pz  = sm + 10048;
    float* red = sm + 10080;
    int* sidx  = (int*)(sm + 10592);
    float* om  = ftT;   // reuse after score phase

    const int g   = blockIdx.x;
    const int b   = g >> 11;
    const int tid = threadIdx.x;
    const int lane = tid & 31, wid = tid >> 5;

    if (tid < 32) {
        const int id = g_gi[(size_t)g * NS + tid];
        sidx[tid] = id;
        const float c0 = g_newxyz[(size_t)g * 3 + 0];
        const float c1 = g_newxyz[(size_t)g * 3 + 1];
        const float c2 = g_newxyz[(size_t)g * 3 + 2];
        const float X = xyz[(size_t)b * 3 * NN + id];
        const float Y = xyz[(size_t)b * 3 * NN + NN + id];
        const float Z = xyz[(size_t)b * 3 * NN + 2 * NN + id];
        px[tid] = X; py[tid] = Y; pz[tid] = Z;
        ft[tid * 68 + 0] = X - c0;
        ft[tid * 68 + 1] = Y - c1;
        ft[tid * 68 + 2] = Z - c2;
    }
    __syncthreads();
    for (int i = tid; i < NS * DINC; i += 256) {
        const int c = i >> 5, j = i & 31;
        ft[j * 68 + 3 + c] = points[(size_t)b * DINC * NN + (size_t)c * NN + sidx[j]];
    }
    __syncthreads();

    // ---- proj: R=4 rows (tgp+8r), 2 dims per thread; 8B weight loads ----
    const int thp = tid & 31;
    const int dp  = thp * 2;
    const int tgp = tid >> 5;       // == wid; rows tgp, tgp+8, tgp+16, tgp+24
    {
        ull aM[4] = {0, 0, 0, 0}, aV[4] = {0, 0, 0, 0};
        const float* mp = g_M1 + dp;
        const float* vp = wv + dp;
#pragma unroll 4
        for (int e = 0; e < 64; ++e) {
            const ull m2 = *(const ull*)(mp + e * 64);
            const ull v2 = *(const ull*)(vp + e * 64);
#pragma unroll
            for (int r = 0; r < 4; ++r) {
                const float f = ft[(tgp + 8 * r) * 68 + e];
                const ull f2 = pack2(f, f);
                aM[r] = ffma2(f2, m2, aM[r]);
                aV[r] = ffma2(f2, v2, aV[r]);
            }
        }
        const ull wx = *(const ull*)(wp + dp);
        const ull wy = *(const ull*)(wp + 64 + dp);
        const ull wz = *(const ull*)(wp + 128 + dp);
        const ull wb = *(const ull*)(bp + dp);
#pragma unroll
        for (int r = 0; r < 4; ++r) {
            const int row = tgp + 8 * r;
            aV[r] = ffma2(pack2(px[row], px[row]), wx, aV[r]);
            aV[r] = ffma2(pack2(py[row], py[row]), wy, aV[r]);
            aV[r] = ffma2(pack2(pz[row], pz[row]), wz, aV[r]);
            aV[r] = fadd2(aV[r], wb);
            *(ull*)&tm[row * 68 + dp] = aM[r];
            *(ull*)&vm[row * 68 + dp] = aV[r];
        }
    }
#pragma unroll
    for (int r = 0; r < 8; ++r) {   // ft -> ftT transpose
        const int idx = tid + r * 256;
        const int e = idx >> 5, j = idx & 31;
        ftT[e * 36 + j] = ft[j * 68 + e];
    }
    __syncthreads();

    // ---- scores: rows ts & ts+16, 2 keys per thread (packed) ----
    const int ths = tid & 15;
    const int ts  = tid >> 4;
    {
        const int j0 = ths * 2;
        ull sA = 0, sB = 0;
        const float* trA = tm + ts * 68;
        const float* trB = tm + (ts + 16) * 68;
#pragma unroll 8
        for (int e = 0; e < 64; ++e) {
            const ull fj = *(const ull*)&ftT[e * 36 + j0];
            sA = ffma2(pack2(trA[e], trA[e]), fj, sA);
            sB = ffma2(pack2(trB[e], trB[e]), fj, sB);
        }
        *(ull*)&sc[ts * 36 + j0]        = sA;
        *(ull*)&sc[(ts + 16) * 36 + j0] = sB;
    }
    __syncthreads();

    for (int rep = 0; rep < 4; ++rep) {   // softmax rows (warp per row)
        const int r = wid * 4 + rep;
        float v = sc[r * 36 + lane];
        float mx = v;
#pragma unroll
        for (int off = 16; off; off >>= 1)
            mx = fmaxf(mx, __shfl_xor_sync(0xffffffffu, mx, off));
        const float pe = __expf(v - mx);
        float ssum = pe;
#pragma unroll
        for (int off = 16; off; off >>= 1)
            ssum += __shfl_xor_sync(0xffffffffu, ssum, off);
        sc[r * 36 + lane] = pe * __fdividef(1.0f, ssum);
    }
    __syncthreads();

    // ---- om = p @ vm (rows ts, ts+16; 4 dims per thread) ----
    {
        const int d0 = ths * 4;
        ull oA0 = 0, oA1 = 0, oB0 = 0, oB1 = 0;
        const float* pA = sc + ts * 36;
        const float* pB = sc + (ts + 16) * 36;
#pragma unroll 4
        for (int j = 0; j < 32; ++j) {
            const ull p0 = pack2(pA[j], pA[j]);
            const ull p1 = pack2(pB[j], pB[j]);
            const ulonglong2 v = *(const ulonglong2*)&vm[j * 68 + d0];
            oA0 = ffma2(p0, v.x, oA0); oA1 = ffma2(p0, v.y, oA1);
            oB0 = ffma2(p1, v.x, oB0); oB1 = ffma2(p1, v.y, oB1);
        }
        *(ull*)&om[ts * 68 + d0]            = oA0;
        *(ull*)&om[ts * 68 + d0 + 2]        = oA1;
        *(ull*)&om[(ts + 16) * 68 + d0]     = oB0;
        *(ull*)&om[(ts + 16) * 68 + d0 + 2] = oB1;
    }
    __syncthreads();

    // ---- z = ft + om @ Wo: R=4 rows, 2 dims; 8B weight loads; fused max ----
    {
        ull z[4];
#pragma unroll
        for (int r = 0; r < 4; ++r)
            z[r] = *(const ull*)&ft[(tgp + 8 * r) * 68 + dp];
        const float* wop = wo + dp;
#pragma unroll 4
        for (int e = 0; e < 64; ++e) {
            const ull w2 = *(const ull*)(wop + e * 64);
#pragma unroll
            for (int r = 0; r < 4; ++r) {
                const float a = om[(tgp + 8 * r) * 68 + e];
                z[r] = ffma2(pack2(a, a), w2, z[r]);
            }
        }
        const float2 z0 = unpack2(z[0]), z1 = unpack2(z[1]);
        const float2 z2 = unpack2(z[2]), z3 = unpack2(z[3]);
        red[tgp * 64 + dp]     = fmaxf(fmaxf(z0.x, z1.x), fmaxf(z2.x, z3.x));
        red[tgp * 64 + dp + 1] = fmaxf(fmaxf(z0.y, z1.y), fmaxf(z2.y, z3.y));
    }
    __syncthreads();
    if (tid < 64) {
        float m = red[tid];
#pragma unroll
        for (int w = 1; w < 8; ++w) m = fmaxf(m, red[w * 64 + tid]);
        g_feat2[(size_t)g * 64 + tid] = m;
    }
}

// ---------------- proj2 (unchanged) ----------------
__global__ void __launch_bounds__(256) proj2_kernel(
    const float* __restrict__ wv2, const float* __restrict__ wp2,
    const float* __restrict__ bp2) {
    __shared__ float ft2[32 * 68];
    __shared__ float Ms[4096], Wv[4096], Wp[192], Bp[64];
    __shared__ float px[32], py[32], pz[32];

    const int b  = blockIdx.x >> 6;
    const int t0 = (blockIdx.x & 63) * 32;
    const int tid = threadIdx.x;

    for (int i = tid; i < 4096; i += 256) { Ms[i] = g_M2[i]; Wv[i] = wv2[i]; }
    if (tid < 192) Wp[tid] = wp2[tid];
    if (tid < 64)  Bp[tid] = bp2[tid];
#pragma unroll
    for (int r = 0; r < 2; ++r) {
        const int f4 = tid + r * 256;
        const int tt = f4 >> 4, c4 = (f4 & 15) * 4;
        *(float4*)&ft2[tt * 68 + c4] =
            *(const float4*)&g_feat2[((size_t)(b * NP + t0 + tt)) * 64 + c4];
    }
    if (tid < 32) {
        px[tid] = g_newxyz[((size_t)(b * NP + t0 + tid)) * 3 + 0];
        py[tid] = g_newxyz[((size_t)(b * NP + t0 + tid)) * 3 + 1];
        pz[tid] = g_newxyz[((size_t)(b * NP + t0 + tid)) * 3 + 2];
    }
    __syncthreads();

    const int t  = tid >> 3;
    const int d0 = (tid & 7) * 8;
    float aq[8] = {0,0,0,0,0,0,0,0};
    float av[8] = {0,0,0,0,0,0,0,0};
    const float* fr = ft2 + t * 68;
#pragma unroll 4
    for (int e = 0; e < 64; ++e) {
        const float f = fr[e];
        const float4 m0 = *(const float4*)&Ms[e * 64 + d0];
        const float4 m1 = *(const float4*)&Ms[e * 64 + d0 + 4];
        const float4 v0 = *(const float4*)&Wv[e * 64 + d0];
        const float4 v1 = *(const float4*)&Wv[e * 64 + d0 + 4];
        aq[0] += f * m0.x; aq[1] += f * m0.y; aq[2] += f * m0.z; aq[3] += f * m0.w;
        aq[4] += f * m1.x; aq[5] += f * m1.y; aq[6] += f * m1.z; aq[7] += f * m1.w;
        av[0] += f * v0.x; av[1] += f * v0.y; av[2] += f * v0.z; av[3] += f * v0.w;
        av[4] += f * v1.x; av[5] += f * v1.y; av[6] += f * v1.z; av[7] += f * v1.w;
    }
    const float X = px[t], Y = py[t], Z = pz[t];
#pragma unroll
    for (int i = 0; i < 8; ++i)
        av[i] += X * Wp[d0 + i] + Y * Wp[64 + d0 + i] + Z * Wp[128 + d0 + i] + Bp[d0 + i];

    const size_t o = ((size_t)(b * NP + t0 + t)) * 64 + d0;
    *(float4*)&g_qp[o]     = make_float4(aq[0], aq[1], aq[2], aq[3]);
    *(float4*)&g_qp[o + 4] = make_float4(aq[4], aq[5], aq[6], aq[7]);
    *(float4*)&g_v[o]      = make_float4(av[0], av[1], av[2], av[3]);
    *(float4*)&g_v[o + 4]  = make_float4(av[4], av[5], av[6], av[7]);
}

// ---------------- attn2 flash: interleaved V + packed AV accumulators ----------------
__global__ void __launch_bounds__(256) flash_kernel() {
    __shared__ float qs[32 * 68];
    __shared__ float ks[32 * 68];
    __shared__ float vs[32 * 68];   // interleaved: vs[j*68 + 2*d] = v[d], +1 = v[d+32]
    __shared__ float ps[8 * 144];

    const int b   = blockIdx.y;
    const int q0  = blockIdx.x * 32;
    const int tid = threadIdx.x;
    const int lane = tid & 31, wid = tid >> 5;

#pragma unroll
    for (int r = 0; r < 2; ++r) {
        const int f4 = tid + r * 256;
        const int tt = f4 >> 4, c4 = (f4 & 15) * 4;
        *(float4*)&qs[tt * 68 + c4] =
            *(const float4*)&g_qp[((size_t)(b * NP + q0 + tt)) * 64 + c4];
    }

    float m0q = -1e30f, m1q = -1e30f, m2q = -1e30f, m3q = -1e30f;
    float l0 = 0.f, l1 = 0.f, l2 = 0.f, l3 = 0.f;
    ull acc0 = 0, acc1 = 0, acc2 = 0, acc3 = 0;

    const float* q0r = qs + (wid * 4 + 0) * 68;
    const float* q1r = qs + (wid * 4 + 1) * 68;
    const float* q2r = qs + (wid * 4 + 2) * 68;
    const float* q3r = qs + (wid * 4 + 3) * 68;
    float* pw = ps + wid * 144;

    // V-interleave loader indices: tt = tid>>3 (row), c8 = (tid&7)*4 (col group)
    const int vtt = tid >> 3, vc8 = (tid & 7) * 4;

    for (int c = 0; c < NP / 32; ++c) {
        __syncthreads();
        const int kb = b * NP + c * 32;
#pragma unroll
        for (int r = 0; r < 2; ++r) {
            const int f4 = tid + r * 256;
            const int tt = f4 >> 4, c4 = (f4 & 15) * 4;
            *(float4*)&ks[tt * 68 + c4] =
                *(const float4*)&g_feat2[((size_t)(kb + tt)) * 64 + c4];
        }
        {
            const size_t vrow = ((size_t)(kb + vtt)) * 64;
            const float4 a = *(const float4*)&g_v[vrow + vc8];
            const float4 bb = *(const float4*)&g_v[vrow + 32 + vc8];
            *(float4*)&vs[vtt * 68 + 2 * vc8]     = make_float4(a.x, bb.x, a.y, bb.y);
            *(float4*)&vs[vtt * 68 + 2 * vc8 + 4] = make_float4(a.z, bb.z, a.w, bb.w);
        }
        __syncthreads();

        ull sp0 = 0, sp1 = 0, sp2 = 0, sp3 = 0;
        const float* krow = ks + lane * 68;
#pragma unroll
        for (int e4 = 0; e4 < 16; ++e4) {
            const ulonglong2 k4 = *(const ulonglong2*)&krow[e4 * 4];
            ulonglong2 a;
            a = *(const ulonglong2*)&q0r[e4 * 4];
            sp0 = ffma2(a.x, k4.x, sp0); sp0 = ffma2(a.y, k4.y, sp0);
            a = *(const ulonglong2*)&q1r[e4 * 4];
            sp1 = ffma2(a.x, k4.x, sp1); sp1 = ffma2(a.y, k4.y, sp1);
            a = *(const ulonglong2*)&q2r[e4 * 4];
            sp2 = ffma2(a.x, k4.x, sp2); sp2 = ffma2(a.y, k4.y, sp2);
            a = *(const ulonglong2*)&q3r[e4 * 4];
            sp3 = ffma2(a.x, k4.x, sp3); sp3 = ffma2(a.y, k4.y, sp3);
        }
        const float2 u0 = unpack2(sp0), u1 = unpack2(sp1);
        const float2 u2 = unpack2(sp2), u3 = unpack2(sp3);
        float s0 = u0.x + u0.y, s1 = u1.x + u1.y, s2 = u2.x + u2.y, s3 = u3.x + u3.y;

#define FLASH_SM(S, M, L, ACC, QQ)                                           \
        {                                                                    \
            float cm = S;                                                    \
            cm = fmaxf(cm, __shfl_xor_sync(0xffffffffu, cm, 16));            \
            cm = fmaxf(cm, __shfl_xor_sync(0xffffffffu, cm, 8));             \
            cm = fmaxf(cm, __shfl_xor_sync(0xffffffffu, cm, 4));             \
            cm = fmaxf(cm, __shfl_xor_sync(0xffffffffu, cm, 2));             \
            cm = fmaxf(cm, __shfl_xor_sync(0xffffffffu, cm, 1));             \
            const float mn = fmaxf(M, cm);                                   \
            const float corr = __expf(M - mn);                               \
            const float pe = __expf(S - mn);                                 \
            float sp = pe;                                                   \
            sp += __shfl_xor_sync(0xffffffffu, sp, 16);                      \
            sp += __shfl_xor_sync(0xffffffffu, sp, 8);                       \
            sp += __shfl_xor_sync(0xffffffffu, sp, 4);                       \
            sp += __shfl_xor_sync(0xffffffffu, sp, 2);                       \
            sp += __shfl_xor_sync(0xffffffffu, sp, 1);                       \
            L = L * corr + sp;                                               \
            ACC = fmul2(ACC, pack2(corr, corr));                             \
            pw[QQ * 36 + lane] = pe;                                         \
            M = mn;                                                          \
        }
        FLASH_SM(s0, m0q, l0, acc0, 0)
        FLASH_SM(s1, m1q, l1, acc1, 1)
        FLASH_SM(s2, m2q, l2, acc2, 2)
        FLASH_SM(s3, m3q, l3, acc3, 3)
#undef FLASH_SM
        __syncwarp();

#pragma unroll
        for (int j4 = 0; j4 < 8; ++j4) {
            float pa0[4], pa1[4], pa2[4], pa3[4];
            *(float4*)pa0 = *(const float4*)&pw[0   + j4 * 4];
            *(float4*)pa1 = *(const float4*)&pw[36  + j4 * 4];
            *(float4*)pa2 = *(const float4*)&pw[72  + j4 * 4];
            *(float4*)pa3 = *(const float4*)&pw[108 + j4 * 4];
#pragma unroll
            for (int jj = 0; jj < 4; ++jj) {
                const int j = j4 * 4 + jj;
                const ull v2 = *(const ull*)&vs[j * 68 + lane * 2];
                acc0 = ffma2(pack2(pa0[jj], pa0[jj]), v2, acc0);
                acc1 = ffma2(pack2(pa1[jj], pa1[jj]), v2, acc1);
                acc2 = ffma2(pack2(pa2[jj], pa2[jj]), v2, acc2);
                acc3 = ffma2(pack2(pa3[jj], pa3[jj]), v2, acc3);
            }
        }
        __syncwarp();
    }

    const size_t ob = ((size_t)(b * NP + q0 + wid * 4)) * 64;
    const float2 o0 = unpack2(acc0), o1 = unpack2(acc1);
    const float2 o2 = unpack2(acc2), o3 = unpack2(acc3);
    g_o[ob + lane]       = o0.x / l0;
    g_o[ob + 32 + lane]  = o0.y / l0;
    g_o[ob + 64 + lane]  = o1.x / l1;
    g_o[ob + 96 + lane]  = o1.y / l1;
    g_o[ob + 128 + lane] = o2.x / l2;
    g_o[ob + 160 + lane] = o2.y / l2;
    g_o[ob + 192 + lane] = o3.x / l3;
    g_o[ob + 224 + lane] = o3.y / l3;
}

// ---------------- final (unchanged) ----------------
__global__ void __launch_bounds__(256) final_kernel(const float* __restrict__ wo,
                                                    float* __restrict__ out2) {
    __shared__ float ot[32 * 68];
    __shared__ float Wo[4096];
    __shared__ float zs[32 * 68];

    const int b  = blockIdx.x >> 6;
    const int t0 = (blockIdx.x & 63) * 32;
    const int tid = threadIdx.x;

    for (int i = tid; i < 4096; i += 256) Wo[i] = wo[i];
#pragma unroll
    for (int r = 0; r < 2; ++r) {
        const int f4 = tid + r * 256;
        const int tt = f4 >> 4, c4 = (f4 & 15) * 4;
        *(float4*)&ot[tt * 68 + c4] =
            *(const float4*)&g_o[((size_t)(b * NP + t0 + tt)) * 64 + c4];
    }
    __syncthreads();

    const int t  = tid >> 3;
    const int d0 = (tid & 7) * 8;
    float z[8];
    {
        const size_t fo = ((size_t)(b * NP + t0 + t)) * 64 + d0;
        const float4 f0 = *(const float4*)&g_feat2[fo];
        const float4 f1 = *(const float4*)&g_feat2[fo + 4];
        z[0] = f0.x; z[1] = f0.y; z[2] = f0.z; z[3] = f0.w;
        z[4] = f1.x; z[5] = f1.y; z[6] = f1.z; z[7] = f1.w;
    }
    const float* orow = ot + t * 68;
#pragma unroll 4
    for (int e = 0; e < 64; ++e) {
        const float a = orow[e];
        const float4 w0 = *(const float4*)&Wo[e * 64 + d0];
        const float4 w1 = *(const float4*)&Wo[e * 64 + d0 + 4];
        z[0] += a * w0.x; z[1] += a * w0.y; z[2] += a * w0.z; z[3] += a * w0.w;
        z[4] += a * w1.x; z[5] += a * w1.y; z[6] += a * w1.z; z[7] += a * w1.w;
    }
    *(float4*)&zs[t * 68 + d0]     = make_float4(z[0], z[1], z[2], z[3]);
    *(float4*)&zs[t * 68 + d0 + 4] = make_float4(z[4], z[5], z[6], z[7]);
    __syncthreads();

    for (int i = tid; i < 2048; i += 256) {
        const int d = i >> 5, tt = i & 31;
        out2[(size_t)b * DD * NP + (size_t)d * NP + t0 + tt] = zs[tt * 68 + d];
    }
}

// ---------------- launch ----------------
extern "C" void kernel_launch(void* const* d_in, const int* in_sizes, int n_in,
                              void* d_out, int out_size) {
    const float* xyz    = (const float*)d_in[0];
    const float* points = (const float*)d_in[1];
    const float* w1q = (const float*)d_in[2];
    const float* w1k = (const float*)d_in[3];
    const float* w1v = (const float*)d_in[4];
    const float* w1o = (const float*)d_in[5];
    const float* w1p = (const float*)d_in[6];
    const float* b1p = (const float*)d_in[7];
    const float* w2q = (const float*)d_in[8];
    const float* w2k = (const float*)d_in[9];
    const float* w2v = (const float*)d_in[10];
    const float* w2o = (const float*)d_in[11];
    const float* w2p = (const float*)d_in[12];
    const float* b2p = (const float*)d_in[13];

    float* out  = (float*)d_out;
    float* out2 = out + (size_t)BB * 3 * NP;

    const int smFps = (3 * NN + 32) * 4 + 8;
    const int smBq  = 3 * NN * 4;

    cudaFuncSetAttribute(fps_kernel,       cudaFuncAttributeMaxDynamicSharedMemorySize, smFps);
    cudaFuncSetAttribute(ballquery_kernel, cudaFuncAttributeMaxDynamicSharedMemorySize, smBq);
    cudaFuncSetAttribute(attn1_kernel,     cudaFuncAttributeMaxDynamicSharedMemorySize, A1_SMEM_BYTES);

    mprep_kernel<<<2, 256>>>(w1q, w1k, w2q, w2k);
    fps_kernel<<<BB, 1024, smFps>>>(xyz, out);
    ballquery_kernel<<<dim3(NP / 8, BB), 256, smBq>>>(xyz);
    attn1_kernel<<<BB * NP, 256, A1_SMEM_BYTES>>>(xyz, points, w1v, w1o, w1p, b1p);
    proj2_kernel<<<BB * 64, 256>>>(w2v, w2p, b2p);
    flash_kernel<<<dim3(NP / 32, BB), 256>>>();
    final_kernel<<<BB * 64, 256>>>(w2o, out2);
}